// round 11
// baseline (speedup 1.0000x reference)
#include <cuda_runtime.h>
#include <cuda_bf16.h>
#include <math.h>
#include <stdint.h>

typedef unsigned long long ull;

// ---------------- problem constants ----------------
#define NB   16
#define HF   128
#define WF   128
#define CF   64
#define CH   704
#define PP   23
#define NPIX (PP*PP)      // 529
#define NROI 176
#define C1N  441          // 21*21
#define C1TOT (NB*64*C1N)
#define NSTEMBLK 8192     // 16 b * 256 rows * 2 halves

// dynamic smem layout for k_stem (u32 offsets)
#define OFF_B    0        // B frags: hi [0,5120), lo [5120,10240)
#define OFF_HI   10240    // A pair table hi: 7*792 = 5544
#define OFF_LO   15784
#define OFF_BHI  21328    // boundary pairs: 7*128 = 896
#define OFF_BLO  22224
#define STEM_SMEM_U32 23120
#define STEM_SMEM_B   (STEM_SMEM_U32*4)

// ---------------- scratch (device globals) ----------------
__device__ float g_stem[(size_t)NB*64*256*256];     // 268 MB fp32 pre-BN
__device__ float g_f  [(size_t)NB*CF*HF*WF];
__device__ float g_xt1[(size_t)NB*CF*HF*WF];
__device__ float g_xt2[(size_t)NB*CF*HF*WF];
__device__ float g_h  [(size_t)NB*CH*NPIX];
__device__ float g_c1p[(size_t)4*C1TOT];
__device__ float g_c1 [(size_t)C1TOT];
__device__ float g_pool[(size_t)NB*64*10*10];
__device__ float g_c2 [(size_t)NB*32*8*8];
__device__ float g_spart_s[64*NSTEMBLK];
__device__ float g_spart_q[64*NSTEMBLK];
__device__ float g_stats_b[64*16*2];
__device__ float g_bn_stem[64*2];
__device__ float g_bn_c1[64*2];

// ---------------- packed f32x2 helpers (conv1) ----------------
__device__ __forceinline__ ull pack2(float lo, float hi) {
    ull r; asm("mov.b64 %0, {%1, %2};" : "=l"(r) : "f"(lo), "f"(hi)); return r;
}
__device__ __forceinline__ void unpack2(float& lo, float& hi, ull v) {
    asm("mov.b64 {%0, %1}, %2;" : "=f"(lo), "=f"(hi) : "l"(v));
}
__device__ __forceinline__ void ffma2(ull& acc, ull a, ull b) {
    asm("fma.rn.f32x2 %0, %1, %2, %0;" : "+l"(acc) : "l"(a), "l"(b));
}

// ---------------- mma.sync helpers (standard PTX) ----------------
__device__ __forceinline__ void mma16816(float* d, const uint32_t* a,
                                         const uint32_t* b) {
    asm volatile(
        "mma.sync.aligned.m16n8k16.row.col.f32.bf16.bf16.f32 "
        "{%0,%1,%2,%3}, {%4,%5,%6,%7}, {%8,%9}, {%0,%1,%2,%3};"
        : "+f"(d[0]), "+f"(d[1]), "+f"(d[2]), "+f"(d[3])
        : "r"(a[0]), "r"(a[1]), "r"(a[2]), "r"(a[3]), "r"(b[0]), "r"(b[1]));
}

__device__ __forceinline__ void bsplit2(float a, float b2, uint32_t& hi, uint32_t& lo) {
    __nv_bfloat16 ha = __float2bfloat16(a), hb = __float2bfloat16(b2);
    float ra = a - __bfloat162float(ha), rb = b2 - __bfloat162float(hb);
    __nv_bfloat16 la = __float2bfloat16(ra), lb = __float2bfloat16(rb);
    hi = (uint32_t)__bfloat16_as_ushort(ha) | ((uint32_t)__bfloat16_as_ushort(hb) << 16);
    lo = (uint32_t)__bfloat16_as_ushort(la) | ((uint32_t)__bfloat16_as_ushort(lb) << 16);
}

// fetch one A-register (bf16x2 pair) from pair tables
__device__ __forceinline__ uint32_t fetchA(const uint32_t* tab, const uint32_t* btab,
                                           int d, int px) {
    if (d & 0x40000000) return 0u;                       // zero pad (k >= 147)
    if (d & 0x20000000) return btab[(d & 0xFFFF)*128 + px];  // ky-boundary pair
    return tab[d + 6*px];
}

// ==================================================================
// Kernel 1: stem conv 7x7 s2 p3 as split-bf16 mma.sync GEMM, smem-fed.
// K remapped: k' = ky*21 + kx*3 + c  (consecutive k' adjacent in NHWC).
// block = 128 threads = 128 consecutive output pixels (half row).
// Warp: 32 px (2 m16 tiles) x 64 oc (8 n8 tiles) x K=160 (10 k16 steps),
// 3 chains (Ahi*Bhi, Ahi*Blo, Alo*Bhi) -> fp32 accum. Fused BN stats.
// ==================================================================
__global__ __launch_bounds__(128) void k_stem(const float* __restrict__ x,
                                              const float* __restrict__ w) {
    extern __shared__ uint32_t sm[];
    __shared__ int s_kdec[160];

    const int tid = threadIdx.x;
    const int lane = tid & 31, warp = tid >> 5;
    const int lq = lane >> 2, lr = lane & 3;
    const int bid = blockIdx.x;
    const int b    = bid >> 9;
    const int rem  = bid & 511;
    const int oy   = rem >> 1;
    const int half = rem & 1;
    const int X0   = half*128;          // first output x of this block
    const int ihb  = 2*oy - 3;          // input row for ky=0
    const int ixb  = 2*X0 - 3;          // input col for ixl=0

    // ---- k' decode LUT ----
    for (int k = tid; k < 160; k += 128) {
        int enc;
        if (k >= 147)            enc = 0x40000000;                 // zero
        else {
            int ky = k / 21, r = k - ky*21;
            if (r == 20)         enc = 0x20000000 | ky;            // boundary pair
            else                 enc = ky*792 + r;
        }
        s_kdec[k] = enc;
    }

    // ---- B fragments (weights, split hi/lo), k remapped ----
    for (int idx = tid; idx < 2560; idx += 128) {
        int l  = idx & 31;
        int nt = (idx >> 5) & 7;
        int ks = idx >> 8;
        int n  = nt*8 + (l >> 2);
        int kb = ks*16 + (l & 3)*2;
        #pragma unroll
        for (int r = 0; r < 2; r++) {
            int k = kb + r*8;
            float w0 = 0.f, w1 = 0.f;
            if (k < 147) {
                int ky = k/21, rr = k - ky*21, kx = rr/3, c = rr - kx*3;
                w0 = __ldg(w + n*147 + c*49 + ky*7 + kx);
            }
            if (k + 1 < 147) {
                int k1 = k + 1;
                int ky = k1/21, rr = k1 - ky*21, kx = rr/3, c = rr - kx*3;
                w1 = __ldg(w + n*147 + c*49 + ky*7 + kx);
            }
            uint32_t hi, lo;
            bsplit2(w0, w1, hi, lo);
            sm[OFF_B + idx*2 + r]        = hi;
            sm[OFF_B + 5120 + idx*2 + r] = lo;
        }
    }

    // ---- A pair tables: s_hi/s_lo[ky*792 + off] = pair(v[off], v[off+1]) ----
    const float* xb = x + (size_t)b*512*512*3;
    for (int i = tid; i < 5544; i += 128) {
        int ky  = i / 792;
        int off = i - ky*792;
        int ih  = ihb + ky;
        bool rowok = ((unsigned)ih < 512u);
        const float* xr = xb + (size_t)ih*1536;    // 512*3
        int ixl0 = off / 3,      c0 = off - ixl0*3;
        int o1 = off + 1;
        int ixl1 = o1 / 3,       c1 = o1 - ixl1*3;
        int ix0 = ixb + ixl0, ix1 = ixb + ixl1;
        float v0 = (rowok && (unsigned)ix0 < 512u) ? __ldg(xr + ix0*3 + c0) : 0.f;
        float v1 = (rowok && (unsigned)ix1 < 512u && o1 < 792)
                   ? __ldg(xr + ix1*3 + c1) : 0.f;
        uint32_t hi, lo;
        bsplit2(v0, v1, hi, lo);
        sm[OFF_HI + i] = hi;
        sm[OFF_LO + i] = lo;
    }

    // ---- boundary pairs: k'=21*ky+20 -> (patch[ky][r=20], patch[ky+1][r=0]) ----
    for (int i = tid; i < 896; i += 128) {
        int ky = i >> 7, px = i & 127;
        int oxg = X0 + px;
        int ih0 = ihb + ky,     ix0v = 2*oxg + 3;   // kx=6, c=2
        int ih1 = ihb + ky + 1, ix1v = 2*oxg - 3;   // kx=0, c=0
        float v0 = ((unsigned)ih0 < 512u && (unsigned)ix0v < 512u)
                   ? __ldg(xb + ((size_t)ih0*512 + ix0v)*3 + 2) : 0.f;
        float v1 = (ky < 6 && (unsigned)ih1 < 512u && (unsigned)ix1v < 512u)
                   ? __ldg(xb + ((size_t)ih1*512 + ix1v)*3) : 0.f;
        uint32_t hi, lo;
        bsplit2(v0, v1, hi, lo);
        sm[OFF_BHI + i] = hi;
        sm[OFF_BLO + i] = lo;
    }
    __syncthreads();

    // ---- MMA mainloop ----
    const uint32_t* t_hi  = sm + OFF_HI;
    const uint32_t* t_lo  = sm + OFF_LO;
    const uint32_t* t_bhi = sm + OFF_BHI;
    const uint32_t* t_blo = sm + OFF_BLO;

    float D[2][8][4];
    #pragma unroll
    for (int t = 0; t < 2; t++)
        #pragma unroll
        for (int nt = 0; nt < 8; nt++)
            #pragma unroll
            for (int j = 0; j < 4; j++) D[t][nt][j] = 0.f;

    #pragma unroll
    for (int ks = 0; ks < 10; ks++) {
        const int d0 = s_kdec[ks*16 + lr*2];
        const int d1 = s_kdec[ks*16 + lr*2 + 8];
        uint32_t ahi[2][4], alo[2][4];
        #pragma unroll
        for (int t = 0; t < 2; t++) {
            int p0 = warp*32 + t*16 + lq, p1 = p0 + 8;
            ahi[t][0] = fetchA(t_hi, t_bhi, d0, p0);
            alo[t][0] = fetchA(t_lo, t_blo, d0, p0);
            ahi[t][1] = fetchA(t_hi, t_bhi, d0, p1);
            alo[t][1] = fetchA(t_lo, t_blo, d0, p1);
            ahi[t][2] = fetchA(t_hi, t_bhi, d1, p0);
            alo[t][2] = fetchA(t_lo, t_blo, d1, p0);
            ahi[t][3] = fetchA(t_hi, t_bhi, d1, p1);
            alo[t][3] = fetchA(t_lo, t_blo, d1, p1);
        }
        #pragma unroll
        for (int nt = 0; nt < 8; nt++) {
            uint32_t bh[2], bl[2];
            int bo = (ks*8 + nt)*64 + lane*2;
            bh[0] = sm[OFF_B + bo];        bh[1] = sm[OFF_B + bo + 1];
            bl[0] = sm[OFF_B + 5120 + bo]; bl[1] = sm[OFF_B + 5120 + bo + 1];
            #pragma unroll
            for (int t = 0; t < 2; t++) {
                mma16816(D[t][nt], ahi[t], bh);
                mma16816(D[t][nt], ahi[t], bl);
                mma16816(D[t][nt], alo[t], bh);
            }
        }
    }
    __syncthreads();   // tables dead; sm becomes D buffer

    // ---- epilogue: gmem store + fused BN partial stats ----
    float* Dbuf = reinterpret_cast<float*>(sm);    // 128 x 65 floats
    #pragma unroll
    for (int t = 0; t < 2; t++) {
        #pragma unroll
        for (int nt = 0; nt < 8; nt++) {
            int oc0 = nt*8 + lr*2;
            int px  = warp*32 + t*16 + lq;
            float* gp = g_stem + ((size_t)(b*64 + oc0)*256 + oy)*256 + half*128;
            gp[px]               = D[t][nt][0];
            gp[65536 + px]       = D[t][nt][1];
            gp[px + 8]           = D[t][nt][2];
            gp[65536 + px + 8]   = D[t][nt][3];
            Dbuf[px*65 + oc0]           = D[t][nt][0];
            Dbuf[px*65 + oc0 + 1]       = D[t][nt][1];
            Dbuf[(px + 8)*65 + oc0]     = D[t][nt][2];
            Dbuf[(px + 8)*65 + oc0 + 1] = D[t][nt][3];
        }
    }
    __syncthreads();
    if (tid < 64) {
        float s = 0.f, q = 0.f;
        #pragma unroll 4
        for (int r2 = 0; r2 < 128; r2++) {
            float v = Dbuf[r2*65 + tid];
            s += v; q += v*v;
        }
        g_spart_s[tid*NSTEMBLK + bid] = s;
        g_spart_q[tid*NSTEMBLK + bid] = q;
    }
}

// ==================================================================
// Kernel 2: combine stem stats -> BN scale/bias (deterministic)
// ==================================================================
__global__ void k_stem_bn_fin(const float* __restrict__ g,
                              const float* __restrict__ bta) {
    __shared__ float ss[256], sq[256];
    int oc = blockIdx.x, t = threadIdx.x;
    float S = 0.f, Q = 0.f;
    #pragma unroll 4
    for (int j = 0; j < 32; j++) {
        int idx = oc*NSTEMBLK + t*32 + j;
        S += g_spart_s[idx];
        Q += g_spart_q[idx];
    }
    ss[t] = S; sq[t] = Q;
    __syncthreads();
    for (int st = 128; st > 0; st >>= 1) {
        if (t < st) { ss[t] += ss[t+st]; sq[t] += sq[t+st]; }
        __syncthreads();
    }
    if (t == 0) {
        const float invN = 1.0f/(16.0f*65536.0f);
        float m  = ss[0]*invN;
        float v  = sq[0]*invN - m*m;
        float sc = g[oc] * rsqrtf(v + 1e-5f);
        g_bn_stem[oc*2 + 0] = sc;
        g_bn_stem[oc*2 + 1] = bta[oc] - m*sc;
    }
}

// ==================================================================
// Kernel 3: BN + ReLU + maxpool 3x3 s2 p1, vectorized (2 outputs/thread)
// ==================================================================
__global__ void k_bnpool3() {
    int idx = blockIdx.x*256 + threadIdx.x;
    if (idx >= NB*CF*HF*64) return;
    int xo2 = idx & 63;
    int yo  = (idx >> 6) & 127;
    int cb  = idx >> 13;
    int c   = cb & 63;
    float sc = g_bn_stem[c*2], bi = g_bn_stem[c*2 + 1];
    const float* p = g_stem + (size_t)cb*65536;
    float m0 = -3.402823466e+38f, m1 = m0;
    #pragma unroll
    for (int ky = 0; ky < 3; ky++) {
        int iy = 2*yo - 1 + ky;
        if (iy < 0 || iy > 255) continue;
        const float* row = p + iy*256;
        float4 qv = *reinterpret_cast<const float4*>(row + 4*xo2);
        float a0 = sc*qv.x + bi, a1 = sc*qv.y + bi;
        float a2 = sc*qv.z + bi, a3 = sc*qv.w + bi;
        if (xo2 > 0) {
            float lf = sc*row[4*xo2 - 1] + bi;
            m0 = fmaxf(m0, lf);
        }
        m0 = fmaxf(m0, fmaxf(a0, a1));
        m1 = fmaxf(m1, fmaxf(a1, fmaxf(a2, a3)));
    }
    float2 outv;
    outv.x = fmaxf(m0, 0.f);
    outv.y = fmaxf(m1, 0.f);
    *reinterpret_cast<float2*>(g_f + (size_t)cb*16384 + yo*128 + 2*xo2) = outv;
}

// ==================================================================
// Kernel 4: grid_sample +/-5 deg, geometry hoisted; block (128,2)
// ==================================================================
__global__ __launch_bounds__(256) void k_gsample() {
    const int xo = threadIdx.x, yo = blockIdx.x;
    const int b = blockIdx.y, which = blockIdx.z;
    const int chalf = threadIdx.y;
    const float C5 = 0.99619469809174553f;
    const float S5 = 0.08715574274765817f;
    float gx = (float)(2*xo + 1) * (1.0f/128.0f) - 1.0f;
    float gy = (float)(2*yo + 1) * (1.0f/128.0f) - 1.0f;
    float g0, g1;
    if (which == 0) { g0 =  C5*gx + S5*gy; g1 = -S5*gx + C5*gy; }
    else            { g0 =  C5*gx - S5*gy; g1 =  S5*gx + C5*gy; }
    float ixf = ((g0 + 1.f)*128.f - 1.f)*0.5f;
    float iyf = ((g1 + 1.f)*128.f - 1.f)*0.5f;
    float x0f = floorf(ixf), y0f = floorf(iyf);
    int x0i = (int)x0f, y0i = (int)y0f;
    float lx = ixf - x0f, ly = iyf - y0f;
    float hx = 1.f - lx,  hy = 1.f - ly;
    bool vx0 = (x0i >= 0) && (x0i < 128);
    bool vx1 = (x0i + 1 >= 0) && (x0i + 1 < 128);
    bool vy0 = (y0i >= 0) && (y0i < 128);
    bool vy1 = (y0i + 1 >= 0) && (y0i + 1 < 128);
    int cx0 = min(max(x0i, 0), 127), cx1 = min(max(x0i + 1, 0), 127);
    int cy0 = min(max(y0i, 0), 127), cy1 = min(max(y0i + 1, 0), 127);
    int o00 = cy0*128 + cx0, o01 = cy0*128 + cx1;
    int o10 = cy1*128 + cx0, o11 = cy1*128 + cx1;
    float w00 = (vx0 && vy0) ? hx*hy : 0.f;
    float w01 = (vx1 && vy0) ? lx*hy : 0.f;
    float w10 = (vx0 && vy1) ? hx*ly : 0.f;
    float w11 = (vx1 && vy1) ? lx*ly : 0.f;

    const float* base = g_f + ((size_t)b*64 + chalf*32)*16384;
    float* dst = (which ? g_xt2 : g_xt1)
               + ((size_t)b*64 + chalf*32)*16384 + yo*128 + xo;
    #pragma unroll 8
    for (int c = 0; c < 32; c++) {
        const float* pl = base + c*16384;
        float v = __ldg(pl + o00)*w00 + __ldg(pl + o01)*w01
                + __ldg(pl + o10)*w10 + __ldg(pl + o11)*w11;
        dst[c*16384] = v;
    }
}

// ==================================================================
// Kernel 5: ROI align (176 rois) -> concat buffer g_h
// ==================================================================
__global__ __launch_bounds__(256) void k_roialign(const float* __restrict__ box) {
    int idx = blockIdx.x*256 + threadIdx.x;
    if (idx >= NROI*4*NPIX) return;
    int p  = idx % NPIX;
    int t2 = idx / NPIX;
    int cq = t2 & 3;
    int r  = t2 >> 2;

    const float* src; int bb, k, och0;
    if (r < 112) { k = r >> 4; bb = r & 15; src = g_f; och0 = k*64; }
    else {
        int u = r - 112; int grp = u >> 4; bb = u & 15; k = grp & 1;
        src = (grp < 2) ? g_xt1 : g_xt2;
        och0 = 448 + grp*64;
    }
    const float* bp = box + bb*28 + k*4;
    float x1 = bp[0]*0.25f, y1v = bp[1]*0.25f, x2 = bp[2]*0.25f, y2 = bp[3]*0.25f;
    float bw = fmaxf(x2 - x1, 1.0f) * (1.0f/23.0f);
    float bh = fmaxf(y2 - y1v, 1.0f) * (1.0f/23.0f);
    int py = p / 23, px = p - py*23;

    int   off[4][4];
    float wt [4][4];
    int sp = 0;
    #pragma unroll
    for (int dy = 0; dy < 2; dy++) {
        float posy = (float)py + 0.25f + 0.5f*(float)dy;
        float yv = y1v + posy*bh;
        bool ey = (yv < -1.0f) || (yv > 128.0f);
        float yc  = fminf(fmaxf(yv, 0.f), 127.f);
        float y0f = floorf(yc);
        int y0 = (int)y0f; int y1i = min(y0 + 1, 127);
        float ly = yc - y0f, hy = 1.f - ly;
        #pragma unroll
        for (int dx = 0; dx < 2; dx++) {
            float posx = (float)px + 0.25f + 0.5f*(float)dx;
            float xv = x1 + posx*bw;
            bool ex = (xv < -1.0f) || (xv > 128.0f);
            float xc  = fminf(fmaxf(xv, 0.f), 127.f);
            float x0f = floorf(xc);
            int x0 = (int)x0f; int x1i = min(x0 + 1, 127);
            float lx = xc - x0f, hx = 1.f - lx;
            float m = (ey || ex) ? 0.f : 1.f;
            off[sp][0] = y0*128  + x0;  wt[sp][0] = hy*hx*m;
            off[sp][1] = y0*128  + x1i; wt[sp][1] = hy*lx*m;
            off[sp][2] = y1i*128 + x0;  wt[sp][2] = ly*hx*m;
            off[sp][3] = y1i*128 + x1i; wt[sp][3] = ly*lx*m;
            sp++;
        }
    }

    const float* plane0 = src + ((size_t)bb*64 + cq*16)*16384;
    float* dst = g_h + ((size_t)bb*CH + och0 + cq*16)*NPIX + p;
    #pragma unroll 2
    for (int c = 0; c < 16; c++) {
        const float* pl = plane0 + c*16384;
        float acc = 0.f;
        #pragma unroll
        for (int s2 = 0; s2 < 4; s2++) {
            float v = __ldg(pl + off[s2][0])*wt[s2][0]
                    + __ldg(pl + off[s2][1])*wt[s2][1]
                    + __ldg(pl + off[s2][2])*wt[s2][2]
                    + __ldg(pl + off[s2][3])*wt[s2][3];
            acc += v;
        }
        dst[c*NPIX] = acc * 0.25f;
    }
}

// ==================================================================
// Kernel 6: conv1 704->64 3x3 valid, K-split x4, f32x2 FFMA, oc pairs
// ==================================================================
__global__ __launch_bounds__(128) void k_conv1(const float* __restrict__ w) {
    __shared__ float s_in[16*529];
    __shared__ ull   s_w2u[576];
    float* s_w2 = (float*)s_w2u;
    const int b = blockIdx.x, ocb = blockIdx.y, ks = blockIdx.z;
    const int tid = threadIdx.x;

    int py[4], px[4]; bool val[4];
    #pragma unroll
    for (int j = 0; j < 4; j++) {
        int p = tid + 128*j;
        val[j] = (p < C1N);
        int pc = val[j] ? p : 0;
        py[j] = pc / 21; px[j] = pc - py[j]*21;
    }

    ull acc2[4][4];
    #pragma unroll
    for (int j = 0; j < 4; j++)
        #pragma unroll
        for (int op = 0; op < 4; op++) acc2[j][op] = 0ull;

    for (int icb = ks*11; icb < ks*11 + 11; icb++) {
        __syncthreads();
        for (int i = tid; i < 16*529; i += 128) {
            int ci = i / 529, pp = i - ci*529;
            s_in[i] = g_h[((size_t)b*CH + icb*16 + ci)*NPIX + pp];
        }
        for (int i = tid; i < 1152; i += 128)
            s_w2[i] = w[(size_t)(ocb*8 + (i & 7))*6336 + icb*144 + (i >> 3)];
        __syncthreads();

        for (int ci = 0; ci < 16; ci++) {
            const float* ip = s_in + ci*529;
            const ull*   wp = &s_w2u[ci*9*4];
            #pragma unroll
            for (int ky = 0; ky < 3; ky++) {
                #pragma unroll
                for (int kx = 0; kx < 3; kx++) {
                    ull iv[4];
                    #pragma unroll
                    for (int j = 0; j < 4; j++) {
                        float t = ip[(py[j] + ky)*23 + px[j] + kx];
                        iv[j] = pack2(t, t);
                    }
                    #pragma unroll
                    for (int op = 0; op < 4; op++) {
                        ull wv = wp[(ky*3 + kx)*4 + op];
                        #pragma unroll
                        for (int j = 0; j < 4; j++) ffma2(acc2[j][op], iv[j], wv);
                    }
                }
            }
        }
    }
    #pragma unroll
    for (int op = 0; op < 4; op++) {
        #pragma unroll
        for (int j = 0; j < 4; j++) {
            float lo, hi; unpack2(lo, hi, acc2[j][op]);
            if (val[j]) {
                int oc0 = ocb*8 + 2*op;
                float* dst = g_c1p + (size_t)ks*C1TOT + ((size_t)b*64)*C1N + tid + 128*j;
                dst[(size_t)oc0*C1N]       = lo;
                dst[(size_t)(oc0 + 1)*C1N] = hi;
            }
        }
    }
}

__global__ void k_c1comb(const float* __restrict__ bias) {
    int idx = blockIdx.x*256 + threadIdx.x;
    if (idx >= C1TOT) return;
    int oc = (idx / C1N) & 63;
    float v = g_c1p[idx] + g_c1p[C1TOT + idx] + g_c1p[2*C1TOT + idx]
            + g_c1p[3*C1TOT + idx] + bias[oc];
    g_c1[idx] = v;
}

// ==================================================================
// conv1 BN stats
// ==================================================================
__global__ void k_stats(const float* __restrict__ src, float* __restrict__ partial,
                        int planeN) {
    int b = blockIdx.x, oc = blockIdx.y;
    const float* p = src + ((size_t)b*64 + oc)*(size_t)planeN;
    float s = 0.f, q = 0.f;
    for (int i = threadIdx.x; i < planeN; i += blockDim.x) {
        float v = p[i]; s += v; q += v*v;
    }
    __shared__ float ss[256], sq[256];
    ss[threadIdx.x] = s; sq[threadIdx.x] = q;
    __syncthreads();
    for (int st = 128; st > 0; st >>= 1) {
        if (threadIdx.x < st) {
            ss[threadIdx.x] += ss[threadIdx.x + st];
            sq[threadIdx.x] += sq[threadIdx.x + st];
        }
        __syncthreads();
    }
    if (threadIdx.x == 0) {
        partial[(oc*16 + b)*2 + 0] = ss[0];
        partial[(oc*16 + b)*2 + 1] = sq[0];
    }
}

__global__ void k_stats_fin(const float* __restrict__ partial,
                            const float* __restrict__ g, const float* __restrict__ bta,
                            float* __restrict__ bn, float invN) {
    int oc = threadIdx.x;
    float s = 0.f, q = 0.f;
    for (int b = 0; b < 16; b++) {
        s += partial[(oc*16 + b)*2 + 0];
        q += partial[(oc*16 + b)*2 + 1];
    }
    float m  = s*invN;
    float v  = q*invN - m*m;
    float sc = g[oc] * rsqrtf(v + 1e-5f);
    bn[oc*2 + 0] = sc;
    bn[oc*2 + 1] = bta[oc] - m*sc;
}

// ==================================================================
// Kernel 7: BN + ReLU + maxpool 2x2 s2
// ==================================================================
__global__ void k_bnpool2() {
    int idx = blockIdx.x*256 + threadIdx.x;
    if (idx >= NB*64*100) return;
    int xo = idx % 10;
    int yo = (idx / 10) % 10;
    int cb = idx / 100;
    int c  = cb & 63;
    float sc = g_bn_c1[c*2], bi = g_bn_c1[c*2 + 1];
    const float* p = g_c1 + (size_t)cb*C1N;
    float m = -3.402823466e+38f;
    #pragma unroll
    for (int dy = 0; dy < 2; dy++)
        #pragma unroll
        for (int dx = 0; dx < 2; dx++) {
            float v = sc*p[(2*yo + dy)*21 + 2*xo + dx] + bi;
            m = fmaxf(m, v);
        }
    g_pool[idx] = fmaxf(m, 0.f);
}

// ==================================================================
// Kernel 8: conv2 64->32 3x3 + ReLU, smem-staged; block per image
// ==================================================================
__global__ __launch_bounds__(256) void k_conv2(const float* __restrict__ w,
                                               const float* __restrict__ bias) {
    __shared__ float s_p[64*100];
    int b = blockIdx.x, t = threadIdx.x;
    for (int i = t; i < 6400; i += 256) s_p[i] = g_pool[(size_t)b*6400 + i];
    __syncthreads();
    int oc = t >> 3, py = t & 7;
    float acc[8];
    float bz = bias[oc];
    #pragma unroll
    for (int px = 0; px < 8; px++) acc[px] = bz;
    for (int ic = 0; ic < 64; ic++) {
        const float* ip = s_p + ic*100 + py*10;
        const float* wp = w + (size_t)oc*576 + ic*9;
        float w0 = wp[0], w1 = wp[1], w2 = wp[2];
        float w3 = wp[3], w4 = wp[4], w5 = wp[5];
        float w6 = wp[6], w7 = wp[7], w8 = wp[8];
        #pragma unroll
        for (int px = 0; px < 8; px++) {
            acc[px] += ip[px]*w0      + ip[px+1]*w1    + ip[px+2]*w2
                     + ip[10+px]*w3   + ip[10+px+1]*w4 + ip[10+px+2]*w5
                     + ip[20+px]*w6   + ip[20+px+1]*w7 + ip[20+px+2]*w8;
        }
    }
    float* dst = g_c2 + (size_t)b*2048 + oc*64 + py*8;
    #pragma unroll
    for (int px = 0; px < 8; px++) dst[px] = fmaxf(acc[px], 0.f);
}

// ==================================================================
// Kernel 9: fc1(2048->128)+ReLU then head(128->12)+tanh
// ==================================================================
__global__ void k_fc(const float* __restrict__ fc1w, const float* __restrict__ fc1b,
                     const float* __restrict__ hw,   const float* __restrict__ hb,
                     float* __restrict__ out) {
    __shared__ float sh[128];
    int b = blockIdx.x, j = threadIdx.x;
    const float* xin = g_c2 + (size_t)b*2048;
    const float* wr  = fc1w + (size_t)j*2048;
    float s = fc1b[j];
    for (int k = 0; k < 2048; k++) s += xin[k]*wr[k];
    sh[j] = fmaxf(s, 0.f);
    __syncthreads();
    if (j < 12) {
        float s2 = hb[j];
        const float* hr = hw + j*128;
        for (int k = 0; k < 128; k++) s2 += sh[k]*hr[k];
        out[b*12 + j] = tanhf(s2);
    }
}

// ==================================================================
extern "C" void kernel_launch(void* const* d_in, const int* in_sizes, int n_in,
                              void* d_out, int out_size) {
    const float* x       = (const float*)d_in[0];
    const float* box     = (const float*)d_in[1];
    const float* stem_w  = (const float*)d_in[2];
    const float* stem_g  = (const float*)d_in[3];
    const float* stem_b  = (const float*)d_in[4];
    const float* conv1_w = (const float*)d_in[5];
    const float* conv1_b = (const float*)d_in[6];
    const float* bn1_g   = (const float*)d_in[7];
    const float* bn1_b   = (const float*)d_in[8];
    const float* conv2_w = (const float*)d_in[9];
    const float* conv2_b = (const float*)d_in[10];
    const float* fc1_w   = (const float*)d_in[11];
    const float* fc1_b   = (const float*)d_in[12];
    const float* head_w  = (const float*)d_in[13];
    const float* head_b  = (const float*)d_in[14];
    float* out = (float*)d_out;

    float *p_stats_b, *p_bn_c1, *p_c1;
    cudaGetSymbolAddress((void**)&p_stats_b, g_stats_b);
    cudaGetSymbolAddress((void**)&p_bn_c1,   g_bn_c1);
    cudaGetSymbolAddress((void**)&p_c1,      g_c1);

    cudaFuncSetAttribute(k_stem, cudaFuncAttributeMaxDynamicSharedMemorySize,
                         STEM_SMEM_B);

    k_stem<<<NSTEMBLK, 128, STEM_SMEM_B>>>(x, stem_w);
    k_stem_bn_fin<<<64, 256>>>(stem_g, stem_b);
    k_bnpool3<<<(NB*CF*HF*64)/256, 256>>>();
    k_gsample<<<dim3(128,16,2), dim3(128,2)>>>();
    k_roialign<<<(NROI*4*NPIX + 255)/256, 256>>>(box);
    k_conv1<<<dim3(16,8,4), 128>>>(conv1_w);
    k_c1comb<<<(C1TOT + 255)/256, 256>>>(conv1_b);
    k_stats<<<dim3(16,64), 256>>>(p_c1, p_stats_b, C1N);
    k_stats_fin<<<1,64>>>(p_stats_b, bn1_g, bn1_b, p_bn_c1, 1.0f/7056.0f);
    k_bnpool2<<<(NB*64*100 + 255)/256, 256>>>();
    k_conv2<<<16, 256>>>(conv2_w, conv2_b);
    k_fc<<<16, 128>>>(fc1_w, fc1_b, head_w, head_b, out);
}

// round 12
// speedup vs baseline: 1.4044x; 1.4044x over previous
#include <cuda_runtime.h>
#include <cuda_bf16.h>
#include <math.h>
#include <stdint.h>

typedef unsigned long long ull;

// ---------------- problem constants ----------------
#define NB   16
#define HF   128
#define WF   128
#define CF   64
#define CH   704
#define PP   23
#define NPIX (PP*PP)      // 529
#define NROI 176
#define C1N  441          // 21*21
#define C1TOT (NB*64*C1N)
#define NSTEMBLK 8192     // 16 b * 256 rows * 2 halves

// dynamic smem layout for k_stem (u32 offsets) — A tables only (51.5 KB)
#define OFF_HI   0        // A pair table hi: 7*792 = 5544
#define OFF_LO   5544
#define OFF_BHI  11088    // boundary pairs: 7*128 = 896
#define OFF_BLO  11984
#define STEM_SMEM_U32 12880
#define STEM_SMEM_B   (STEM_SMEM_U32*4)

// ---------------- scratch (device globals) ----------------
__device__ float g_stem[(size_t)NB*64*256*256];     // 268 MB fp32 pre-BN
__device__ float g_f  [(size_t)NB*CF*HF*WF];
__device__ float g_xt1[(size_t)NB*CF*HF*WF];
__device__ float g_xt2[(size_t)NB*CF*HF*WF];
__device__ float g_h  [(size_t)NB*CH*NPIX];
__device__ float g_c1p[(size_t)4*C1TOT];
__device__ float g_c1 [(size_t)C1TOT];
__device__ float g_pool[(size_t)NB*64*10*10];
__device__ float g_c2 [(size_t)NB*32*8*8];
__device__ float g_spart_s[64*NSTEMBLK];
__device__ float g_spart_q[64*NSTEMBLK];
__device__ float g_stats_b[64*16*2];
__device__ float g_bn_stem[64*2];
__device__ float g_bn_c1[64*2];
__device__ uint32_t g_bfrag[10240];                 // B frags: hi [0,5120), lo [5120,10240)

// ---------------- packed f32x2 helpers (conv1) ----------------
__device__ __forceinline__ ull pack2(float lo, float hi) {
    ull r; asm("mov.b64 %0, {%1, %2};" : "=l"(r) : "f"(lo), "f"(hi)); return r;
}
__device__ __forceinline__ void unpack2(float& lo, float& hi, ull v) {
    asm("mov.b64 {%0, %1}, %2;" : "=f"(lo), "=f"(hi) : "l"(v));
}
__device__ __forceinline__ void ffma2(ull& acc, ull a, ull b) {
    asm("fma.rn.f32x2 %0, %1, %2, %0;" : "+l"(acc) : "l"(a), "l"(b));
}

// ---------------- mma.sync helpers (standard PTX) ----------------
__device__ __forceinline__ void mma16816(float* d, const uint32_t* a,
                                         const uint32_t* b) {
    asm volatile(
        "mma.sync.aligned.m16n8k16.row.col.f32.bf16.bf16.f32 "
        "{%0,%1,%2,%3}, {%4,%5,%6,%7}, {%8,%9}, {%0,%1,%2,%3};"
        : "+f"(d[0]), "+f"(d[1]), "+f"(d[2]), "+f"(d[3])
        : "r"(a[0]), "r"(a[1]), "r"(a[2]), "r"(a[3]), "r"(b[0]), "r"(b[1]));
}

__device__ __forceinline__ void bsplit2(float a, float b2, uint32_t& hi, uint32_t& lo) {
    __nv_bfloat16 ha = __float2bfloat16(a), hb = __float2bfloat16(b2);
    float ra = a - __bfloat162float(ha), rb = b2 - __bfloat162float(hb);
    __nv_bfloat16 la = __float2bfloat16(ra), lb = __float2bfloat16(rb);
    hi = (uint32_t)__bfloat16_as_ushort(ha) | ((uint32_t)__bfloat16_as_ushort(hb) << 16);
    lo = (uint32_t)__bfloat16_as_ushort(la) | ((uint32_t)__bfloat16_as_ushort(lb) << 16);
}

// fetch one A-register (bf16x2 pair) from pair tables
__device__ __forceinline__ uint32_t fetchA(const uint32_t* tab, const uint32_t* btab,
                                           int d, int px) {
    if (d & 0x40000000) return 0u;                       // zero pad (k >= 147)
    if (d & 0x20000000) return btab[(d & 0xFFFF)*128 + px];  // ky-boundary pair
    return tab[d + 6*px];
}

// ==================================================================
// Kernel 0: precompute B fragments (weights, split hi/lo, k'-remapped)
// once per launch -> g_bfrag. grid 20 x 128.
// ==================================================================
__global__ void k_bfrag(const float* __restrict__ w) {
    int idx = blockIdx.x*128 + threadIdx.x;
    if (idx >= 2560) return;
    int l  = idx & 31;
    int nt = (idx >> 5) & 7;
    int ks = idx >> 8;
    int n  = nt*8 + (l >> 2);
    int kb = ks*16 + (l & 3)*2;
    #pragma unroll
    for (int r = 0; r < 2; r++) {
        int k = kb + r*8;
        float w0 = 0.f, w1 = 0.f;
        if (k < 147) {
            int ky = k/21, rr = k - ky*21, kx = rr/3, c = rr - kx*3;
            w0 = __ldg(w + n*147 + c*49 + ky*7 + kx);
        }
        if (k + 1 < 147) {
            int k1 = k + 1;
            int ky = k1/21, rr = k1 - ky*21, kx = rr/3, c = rr - kx*3;
            w1 = __ldg(w + n*147 + c*49 + ky*7 + kx);
        }
        uint32_t hi, lo;
        bsplit2(w0, w1, hi, lo);
        g_bfrag[idx*2 + r]        = hi;
        g_bfrag[5120 + idx*2 + r] = lo;
    }
}

// ==================================================================
// Kernel 1: stem conv 7x7 s2 p3 as split-bf16 mma.sync GEMM, smem-fed A,
// gmem-fed (L1-hot) B fragments. K remapped: k' = ky*21 + kx*3 + c.
// block = 128 threads = 128 consecutive output pixels (half row).
// Warp: 32 px (2 m16) x 64 oc (8 n8) x K=160 (10 k16), 3 chains.
// ==================================================================
__global__ __launch_bounds__(128) void k_stem(const float* __restrict__ x) {
    extern __shared__ uint32_t sm[];
    __shared__ int s_kdec[160];

    const int tid = threadIdx.x;
    const int lane = tid & 31, warp = tid >> 5;
    const int lq = lane >> 2, lr = lane & 3;
    const int bid = blockIdx.x;
    const int b    = bid >> 9;
    const int rem  = bid & 511;
    const int oy   = rem >> 1;
    const int half = rem & 1;
    const int X0   = half*128;
    const int ihb  = 2*oy - 3;
    const int ixb  = 2*X0 - 3;

    // k' decode LUT
    for (int k = tid; k < 160; k += 128) {
        int enc;
        if (k >= 147)  enc = 0x40000000;
        else {
            int ky = k / 21, r = k - ky*21;
            if (r == 20) enc = 0x20000000 | ky;
            else         enc = ky*792 + r;
        }
        s_kdec[k] = enc;
    }

    // A pair tables
    const float* xb = x + (size_t)b*512*512*3;
    for (int i = tid; i < 5544; i += 128) {
        int ky  = i / 792;
        int off = i - ky*792;
        int ih  = ihb + ky;
        bool rowok = ((unsigned)ih < 512u);
        const float* xr = xb + (size_t)ih*1536;
        int ixl0 = off / 3,      c0 = off - ixl0*3;
        int o1 = off + 1;
        int ixl1 = o1 / 3,       c1 = o1 - ixl1*3;
        int ix0 = ixb + ixl0, ix1 = ixb + ixl1;
        float v0 = (rowok && (unsigned)ix0 < 512u) ? __ldg(xr + ix0*3 + c0) : 0.f;
        float v1 = (rowok && (unsigned)ix1 < 512u && o1 < 792)
                   ? __ldg(xr + ix1*3 + c1) : 0.f;
        uint32_t hi, lo;
        bsplit2(v0, v1, hi, lo);
        sm[OFF_HI + i] = hi;
        sm[OFF_LO + i] = lo;
    }

    // boundary pairs: k'=21*ky+20 -> (patch[ky][20], patch[ky+1][0])
    for (int i = tid; i < 896; i += 128) {
        int ky = i >> 7, px = i & 127;
        int oxg = X0 + px;
        int ih0 = ihb + ky,     ix0v = 2*oxg + 3;
        int ih1 = ihb + ky + 1, ix1v = 2*oxg - 3;
        float v0 = ((unsigned)ih0 < 512u && (unsigned)ix0v < 512u)
                   ? __ldg(xb + ((size_t)ih0*512 + ix0v)*3 + 2) : 0.f;
        float v1 = (ky < 6 && (unsigned)ih1 < 512u && (unsigned)ix1v < 512u)
                   ? __ldg(xb + ((size_t)ih1*512 + ix1v)*3) : 0.f;
        uint32_t hi, lo;
        bsplit2(v0, v1, hi, lo);
        sm[OFF_BHI + i] = hi;
        sm[OFF_BLO + i] = lo;
    }
    __syncthreads();

    const uint32_t* t_hi  = sm + OFF_HI;
    const uint32_t* t_lo  = sm + OFF_LO;
    const uint32_t* t_bhi = sm + OFF_BHI;
    const uint32_t* t_blo = sm + OFF_BLO;

    float D[2][8][4];
    #pragma unroll
    for (int t = 0; t < 2; t++)
        #pragma unroll
        for (int nt = 0; nt < 8; nt++)
            #pragma unroll
            for (int j = 0; j < 4; j++) D[t][nt][j] = 0.f;

    #pragma unroll
    for (int ks = 0; ks < 10; ks++) {
        const int d0 = s_kdec[ks*16 + lr*2];
        const int d1 = s_kdec[ks*16 + lr*2 + 8];
        uint32_t ahi[2][4], alo[2][4];
        #pragma unroll
        for (int t = 0; t < 2; t++) {
            int p0 = warp*32 + t*16 + lq, p1 = p0 + 8;
            ahi[t][0] = fetchA(t_hi, t_bhi, d0, p0);
            alo[t][0] = fetchA(t_lo, t_blo, d0, p0);
            ahi[t][1] = fetchA(t_hi, t_bhi, d0, p1);
            alo[t][1] = fetchA(t_lo, t_blo, d0, p1);
            ahi[t][2] = fetchA(t_hi, t_bhi, d1, p0);
            alo[t][2] = fetchA(t_lo, t_blo, d1, p0);
            ahi[t][3] = fetchA(t_hi, t_bhi, d1, p1);
            alo[t][3] = fetchA(t_lo, t_blo, d1, p1);
        }
        #pragma unroll
        for (int nt = 0; nt < 8; nt++) {
            uint32_t bh[2], bl[2];
            int bo = (ks*8 + nt)*64 + lane*2;
            bh[0] = __ldg(g_bfrag + bo);        bh[1] = __ldg(g_bfrag + bo + 1);
            bl[0] = __ldg(g_bfrag + 5120 + bo); bl[1] = __ldg(g_bfrag + 5120 + bo + 1);
            #pragma unroll
            for (int t = 0; t < 2; t++) {
                mma16816(D[t][nt], ahi[t], bh);
                mma16816(D[t][nt], ahi[t], bl);
                mma16816(D[t][nt], alo[t], bh);
            }
        }
    }
    __syncthreads();   // tables dead; sm becomes D buffer

    // epilogue: gmem store + fused BN partial stats
    float* Dbuf = reinterpret_cast<float*>(sm);    // 128 x 65 floats
    #pragma unroll
    for (int t = 0; t < 2; t++) {
        #pragma unroll
        for (int nt = 0; nt < 8; nt++) {
            int oc0 = nt*8 + lr*2;
            int px  = warp*32 + t*16 + lq;
            float* gp = g_stem + ((size_t)(b*64 + oc0)*256 + oy)*256 + half*128;
            gp[px]               = D[t][nt][0];
            gp[65536 + px]       = D[t][nt][1];
            gp[px + 8]           = D[t][nt][2];
            gp[65536 + px + 8]   = D[t][nt][3];
            Dbuf[px*65 + oc0]           = D[t][nt][0];
            Dbuf[px*65 + oc0 + 1]       = D[t][nt][1];
            Dbuf[(px + 8)*65 + oc0]     = D[t][nt][2];
            Dbuf[(px + 8)*65 + oc0 + 1] = D[t][nt][3];
        }
    }
    __syncthreads();
    if (tid < 64) {
        float s = 0.f, q = 0.f;
        #pragma unroll 4
        for (int r2 = 0; r2 < 128; r2++) {
            float v = Dbuf[r2*65 + tid];
            s += v; q += v*v;
        }
        g_spart_s[tid*NSTEMBLK + bid] = s;
        g_spart_q[tid*NSTEMBLK + bid] = q;
    }
}

// ==================================================================
// Kernel 2: combine stem stats -> BN scale/bias (deterministic)
// ==================================================================
__global__ void k_stem_bn_fin(const float* __restrict__ g,
                              const float* __restrict__ bta) {
    __shared__ float ss[256], sq[256];
    int oc = blockIdx.x, t = threadIdx.x;
    float S = 0.f, Q = 0.f;
    #pragma unroll 4
    for (int j = 0; j < 32; j++) {
        int idx = oc*NSTEMBLK + t*32 + j;
        S += g_spart_s[idx];
        Q += g_spart_q[idx];
    }
    ss[t] = S; sq[t] = Q;
    __syncthreads();
    for (int st = 128; st > 0; st >>= 1) {
        if (t < st) { ss[t] += ss[t+st]; sq[t] += sq[t+st]; }
        __syncthreads();
    }
    if (t == 0) {
        const float invN = 1.0f/(16.0f*65536.0f);
        float m  = ss[0]*invN;
        float v  = sq[0]*invN - m*m;
        float sc = g[oc] * rsqrtf(v + 1e-5f);
        g_bn_stem[oc*2 + 0] = sc;
        g_bn_stem[oc*2 + 1] = bta[oc] - m*sc;
    }
}

// ==================================================================
// Kernel 3: BN + ReLU + maxpool 3x3 s2 p1, vectorized (2 outputs/thread)
// ==================================================================
__global__ void k_bnpool3() {
    int idx = blockIdx.x*256 + threadIdx.x;
    if (idx >= NB*CF*HF*64) return;
    int xo2 = idx & 63;
    int yo  = (idx >> 6) & 127;
    int cb  = idx >> 13;
    int c   = cb & 63;
    float sc = g_bn_stem[c*2], bi = g_bn_stem[c*2 + 1];
    const float* p = g_stem + (size_t)cb*65536;
    float m0 = -3.402823466e+38f, m1 = m0;
    #pragma unroll
    for (int ky = 0; ky < 3; ky++) {
        int iy = 2*yo - 1 + ky;
        if (iy < 0 || iy > 255) continue;
        const float* row = p + iy*256;
        float4 qv = *reinterpret_cast<const float4*>(row + 4*xo2);
        float a0 = sc*qv.x + bi, a1 = sc*qv.y + bi;
        float a2 = sc*qv.z + bi, a3 = sc*qv.w + bi;
        if (xo2 > 0) {
            float lf = sc*row[4*xo2 - 1] + bi;
            m0 = fmaxf(m0, lf);
        }
        m0 = fmaxf(m0, fmaxf(a0, a1));
        m1 = fmaxf(m1, fmaxf(a1, fmaxf(a2, a3)));
    }
    float2 outv;
    outv.x = fmaxf(m0, 0.f);
    outv.y = fmaxf(m1, 0.f);
    *reinterpret_cast<float2*>(g_f + (size_t)cb*16384 + yo*128 + 2*xo2) = outv;
}

// ==================================================================
// Kernel 4: grid_sample +/-5 deg, geometry hoisted; block (128,2)
// ==================================================================
__global__ __launch_bounds__(256) void k_gsample() {
    const int xo = threadIdx.x, yo = blockIdx.x;
    const int b = blockIdx.y, which = blockIdx.z;
    const int chalf = threadIdx.y;
    const float C5 = 0.99619469809174553f;
    const float S5 = 0.08715574274765817f;
    float gx = (float)(2*xo + 1) * (1.0f/128.0f) - 1.0f;
    float gy = (float)(2*yo + 1) * (1.0f/128.0f) - 1.0f;
    float g0, g1;
    if (which == 0) { g0 =  C5*gx + S5*gy; g1 = -S5*gx + C5*gy; }
    else            { g0 =  C5*gx - S5*gy; g1 =  S5*gx + C5*gy; }
    float ixf = ((g0 + 1.f)*128.f - 1.f)*0.5f;
    float iyf = ((g1 + 1.f)*128.f - 1.f)*0.5f;
    float x0f = floorf(ixf), y0f = floorf(iyf);
    int x0i = (int)x0f, y0i = (int)y0f;
    float lx = ixf - x0f, ly = iyf - y0f;
    float hx = 1.f - lx,  hy = 1.f - ly;
    bool vx0 = (x0i >= 0) && (x0i < 128);
    bool vx1 = (x0i + 1 >= 0) && (x0i + 1 < 128);
    bool vy0 = (y0i >= 0) && (y0i < 128);
    bool vy1 = (y0i + 1 >= 0) && (y0i + 1 < 128);
    int cx0 = min(max(x0i, 0), 127), cx1 = min(max(x0i + 1, 0), 127);
    int cy0 = min(max(y0i, 0), 127), cy1 = min(max(y0i + 1, 0), 127);
    int o00 = cy0*128 + cx0, o01 = cy0*128 + cx1;
    int o10 = cy1*128 + cx0, o11 = cy1*128 + cx1;
    float w00 = (vx0 && vy0) ? hx*hy : 0.f;
    float w01 = (vx1 && vy0) ? lx*hy : 0.f;
    float w10 = (vx0 && vy1) ? hx*ly : 0.f;
    float w11 = (vx1 && vy1) ? lx*ly : 0.f;

    const float* base = g_f + ((size_t)b*64 + chalf*32)*16384;
    float* dst = (which ? g_xt2 : g_xt1)
               + ((size_t)b*64 + chalf*32)*16384 + yo*128 + xo;
    #pragma unroll 8
    for (int c = 0; c < 32; c++) {
        const float* pl = base + c*16384;
        float v = __ldg(pl + o00)*w00 + __ldg(pl + o01)*w01
                + __ldg(pl + o10)*w10 + __ldg(pl + o11)*w11;
        dst[c*16384] = v;
    }
}

// ==================================================================
// Kernel 5: ROI align (176 rois) -> concat buffer g_h
// ==================================================================
__global__ __launch_bounds__(256) void k_roialign(const float* __restrict__ box) {
    int idx = blockIdx.x*256 + threadIdx.x;
    if (idx >= NROI*4*NPIX) return;
    int p  = idx % NPIX;
    int t2 = idx / NPIX;
    int cq = t2 & 3;
    int r  = t2 >> 2;

    const float* src; int bb, k, och0;
    if (r < 112) { k = r >> 4; bb = r & 15; src = g_f; och0 = k*64; }
    else {
        int u = r - 112; int grp = u >> 4; bb = u & 15; k = grp & 1;
        src = (grp < 2) ? g_xt1 : g_xt2;
        och0 = 448 + grp*64;
    }
    const float* bp = box + bb*28 + k*4;
    float x1 = bp[0]*0.25f, y1v = bp[1]*0.25f, x2 = bp[2]*0.25f, y2 = bp[3]*0.25f;
    float bw = fmaxf(x2 - x1, 1.0f) * (1.0f/23.0f);
    float bh = fmaxf(y2 - y1v, 1.0f) * (1.0f/23.0f);
    int py = p / 23, px = p - py*23;

    int   off[4][4];
    float wt [4][4];
    int sp = 0;
    #pragma unroll
    for (int dy = 0; dy < 2; dy++) {
        float posy = (float)py + 0.25f + 0.5f*(float)dy;
        float yv = y1v + posy*bh;
        bool ey = (yv < -1.0f) || (yv > 128.0f);
        float yc  = fminf(fmaxf(yv, 0.f), 127.f);
        float y0f = floorf(yc);
        int y0 = (int)y0f; int y1i = min(y0 + 1, 127);
        float ly = yc - y0f, hy = 1.f - ly;
        #pragma unroll
        for (int dx = 0; dx < 2; dx++) {
            float posx = (float)px + 0.25f + 0.5f*(float)dx;
            float xv = x1 + posx*bw;
            bool ex = (xv < -1.0f) || (xv > 128.0f);
            float xc  = fminf(fmaxf(xv, 0.f), 127.f);
            float x0f = floorf(xc);
            int x0 = (int)x0f; int x1i = min(x0 + 1, 127);
            float lx = xc - x0f, hx = 1.f - lx;
            float m = (ey || ex) ? 0.f : 1.f;
            off[sp][0] = y0*128  + x0;  wt[sp][0] = hy*hx*m;
            off[sp][1] = y0*128  + x1i; wt[sp][1] = hy*lx*m;
            off[sp][2] = y1i*128 + x0;  wt[sp][2] = ly*hx*m;
            off[sp][3] = y1i*128 + x1i; wt[sp][3] = ly*lx*m;
            sp++;
        }
    }

    const float* plane0 = src + ((size_t)bb*64 + cq*16)*16384;
    float* dst = g_h + ((size_t)bb*CH + och0 + cq*16)*NPIX + p;
    #pragma unroll 2
    for (int c = 0; c < 16; c++) {
        const float* pl = plane0 + c*16384;
        float acc = 0.f;
        #pragma unroll
        for (int s2 = 0; s2 < 4; s2++) {
            float v = __ldg(pl + off[s2][0])*wt[s2][0]
                    + __ldg(pl + off[s2][1])*wt[s2][1]
                    + __ldg(pl + off[s2][2])*wt[s2][2]
                    + __ldg(pl + off[s2][3])*wt[s2][3];
            acc += v;
        }
        dst[c*NPIX] = acc * 0.25f;
    }
}

// ==================================================================
// Kernel 6: conv1 704->64 3x3 valid, K-split x4, f32x2 FFMA, oc pairs
// ==================================================================
__global__ __launch_bounds__(128) void k_conv1(const float* __restrict__ w) {
    __shared__ float s_in[16*529];
    __shared__ ull   s_w2u[576];
    float* s_w2 = (float*)s_w2u;
    const int b = blockIdx.x, ocb = blockIdx.y, ks = blockIdx.z;
    const int tid = threadIdx.x;

    int py[4], px[4]; bool val[4];
    #pragma unroll
    for (int j = 0; j < 4; j++) {
        int p = tid + 128*j;
        val[j] = (p < C1N);
        int pc = val[j] ? p : 0;
        py[j] = pc / 21; px[j] = pc - py[j]*21;
    }

    ull acc2[4][4];
    #pragma unroll
    for (int j = 0; j < 4; j++)
        #pragma unroll
        for (int op = 0; op < 4; op++) acc2[j][op] = 0ull;

    for (int icb = ks*11; icb < ks*11 + 11; icb++) {
        __syncthreads();
        for (int i = tid; i < 16*529; i += 128) {
            int ci = i / 529, pp = i - ci*529;
            s_in[i] = g_h[((size_t)b*CH + icb*16 + ci)*NPIX + pp];
        }
        for (int i = tid; i < 1152; i += 128)
            s_w2[i] = w[(size_t)(ocb*8 + (i & 7))*6336 + icb*144 + (i >> 3)];
        __syncthreads();

        for (int ci = 0; ci < 16; ci++) {
            const float* ip = s_in + ci*529;
            const ull*   wp = &s_w2u[ci*9*4];
            #pragma unroll
            for (int ky = 0; ky < 3; ky++) {
                #pragma unroll
                for (int kx = 0; kx < 3; kx++) {
                    ull iv[4];
                    #pragma unroll
                    for (int j = 0; j < 4; j++) {
                        float t = ip[(py[j] + ky)*23 + px[j] + kx];
                        iv[j] = pack2(t, t);
                    }
                    #pragma unroll
                    for (int op = 0; op < 4; op++) {
                        ull wv = wp[(ky*3 + kx)*4 + op];
                        #pragma unroll
                        for (int j = 0; j < 4; j++) ffma2(acc2[j][op], iv[j], wv);
                    }
                }
            }
        }
    }
    #pragma unroll
    for (int op = 0; op < 4; op++) {
        #pragma unroll
        for (int j = 0; j < 4; j++) {
            float lo, hi; unpack2(lo, hi, acc2[j][op]);
            if (val[j]) {
                int oc0 = ocb*8 + 2*op;
                float* dst = g_c1p + (size_t)ks*C1TOT + ((size_t)b*64)*C1N + tid + 128*j;
                dst[(size_t)oc0*C1N]       = lo;
                dst[(size_t)(oc0 + 1)*C1N] = hi;
            }
        }
    }
}

__global__ void k_c1comb(const float* __restrict__ bias) {
    int idx = blockIdx.x*256 + threadIdx.x;
    if (idx >= C1TOT) return;
    int oc = (idx / C1N) & 63;
    float v = g_c1p[idx] + g_c1p[C1TOT + idx] + g_c1p[2*C1TOT + idx]
            + g_c1p[3*C1TOT + idx] + bias[oc];
    g_c1[idx] = v;
}

// ==================================================================
// conv1 BN stats
// ==================================================================
__global__ void k_stats(const float* __restrict__ src, float* __restrict__ partial,
                        int planeN) {
    int b = blockIdx.x, oc = blockIdx.y;
    const float* p = src + ((size_t)b*64 + oc)*(size_t)planeN;
    float s = 0.f, q = 0.f;
    for (int i = threadIdx.x; i < planeN; i += blockDim.x) {
        float v = p[i]; s += v; q += v*v;
    }
    __shared__ float ss[256], sq[256];
    ss[threadIdx.x] = s; sq[threadIdx.x] = q;
    __syncthreads();
    for (int st = 128; st > 0; st >>= 1) {
        if (threadIdx.x < st) {
            ss[threadIdx.x] += ss[threadIdx.x + st];
            sq[threadIdx.x] += sq[threadIdx.x + st];
        }
        __syncthreads();
    }
    if (threadIdx.x == 0) {
        partial[(oc*16 + b)*2 + 0] = ss[0];
        partial[(oc*16 + b)*2 + 1] = sq[0];
    }
}

__global__ void k_stats_fin(const float* __restrict__ partial,
                            const float* __restrict__ g, const float* __restrict__ bta,
                            float* __restrict__ bn, float invN) {
    int oc = threadIdx.x;
    float s = 0.f, q = 0.f;
    for (int b = 0; b < 16; b++) {
        s += partial[(oc*16 + b)*2 + 0];
        q += partial[(oc*16 + b)*2 + 1];
    }
    float m  = s*invN;
    float v  = q*invN - m*m;
    float sc = g[oc] * rsqrtf(v + 1e-5f);
    bn[oc*2 + 0] = sc;
    bn[oc*2 + 1] = bta[oc] - m*sc;
}

// ==================================================================
// Kernel 7: BN + ReLU + maxpool 2x2 s2
// ==================================================================
__global__ void k_bnpool2() {
    int idx = blockIdx.x*256 + threadIdx.x;
    if (idx >= NB*64*100) return;
    int xo = idx % 10;
    int yo = (idx / 10) % 10;
    int cb = idx / 100;
    int c  = cb & 63;
    float sc = g_bn_c1[c*2], bi = g_bn_c1[c*2 + 1];
    const float* p = g_c1 + (size_t)cb*C1N;
    float m = -3.402823466e+38f;
    #pragma unroll
    for (int dy = 0; dy < 2; dy++)
        #pragma unroll
        for (int dx = 0; dx < 2; dx++) {
            float v = sc*p[(2*yo + dy)*21 + 2*xo + dx] + bi;
            m = fmaxf(m, v);
        }
    g_pool[idx] = fmaxf(m, 0.f);
}

// ==================================================================
// Kernel 8: conv2 64->32 3x3 + ReLU, smem-staged; block per image
// ==================================================================
__global__ __launch_bounds__(256) void k_conv2(const float* __restrict__ w,
                                               const float* __restrict__ bias) {
    __shared__ float s_p[64*100];
    int b = blockIdx.x, t = threadIdx.x;
    for (int i = t; i < 6400; i += 256) s_p[i] = g_pool[(size_t)b*6400 + i];
    __syncthreads();
    int oc = t >> 3, py = t & 7;
    float acc[8];
    float bz = bias[oc];
    #pragma unroll
    for (int px = 0; px < 8; px++) acc[px] = bz;
    for (int ic = 0; ic < 64; ic++) {
        const float* ip = s_p + ic*100 + py*10;
        const float* wp = w + (size_t)oc*576 + ic*9;
        float w0 = wp[0], w1 = wp[1], w2 = wp[2];
        float w3 = wp[3], w4 = wp[4], w5 = wp[5];
        float w6 = wp[6], w7 = wp[7], w8 = wp[8];
        #pragma unroll
        for (int px = 0; px < 8; px++) {
            acc[px] += ip[px]*w0      + ip[px+1]*w1    + ip[px+2]*w2
                     + ip[10+px]*w3   + ip[10+px+1]*w4 + ip[10+px+2]*w5
                     + ip[20+px]*w6   + ip[20+px+1]*w7 + ip[20+px+2]*w8;
        }
    }
    float* dst = g_c2 + (size_t)b*2048 + oc*64 + py*8;
    #pragma unroll
    for (int px = 0; px < 8; px++) dst[px] = fmaxf(acc[px], 0.f);
}

// ==================================================================
// Kernel 9: fc1(2048->128)+ReLU then head(128->12)+tanh
// ==================================================================
__global__ void k_fc(const float* __restrict__ fc1w, const float* __restrict__ fc1b,
                     const float* __restrict__ hw,   const float* __restrict__ hb,
                     float* __restrict__ out) {
    __shared__ float sh[128];
    int b = blockIdx.x, j = threadIdx.x;
    const float* xin = g_c2 + (size_t)b*2048;
    const float* wr  = fc1w + (size_t)j*2048;
    float s = fc1b[j];
    for (int k = 0; k < 2048; k++) s += xin[k]*wr[k];
    sh[j] = fmaxf(s, 0.f);
    __syncthreads();
    if (j < 12) {
        float s2 = hb[j];
        const float* hr = hw + j*128;
        for (int k = 0; k < 128; k++) s2 += sh[k]*hr[k];
        out[b*12 + j] = tanhf(s2);
    }
}

// ==================================================================
extern "C" void kernel_launch(void* const* d_in, const int* in_sizes, int n_in,
                              void* d_out, int out_size) {
    const float* x       = (const float*)d_in[0];
    const float* box     = (const float*)d_in[1];
    const float* stem_w  = (const float*)d_in[2];
    const float* stem_g  = (const float*)d_in[3];
    const float* stem_b  = (const float*)d_in[4];
    const float* conv1_w = (const float*)d_in[5];
    const float* conv1_b = (const float*)d_in[6];
    const float* bn1_g   = (const float*)d_in[7];
    const float* bn1_b   = (const float*)d_in[8];
    const float* conv2_w = (const float*)d_in[9];
    const float* conv2_b = (const float*)d_in[10];
    const float* fc1_w   = (const float*)d_in[11];
    const float* fc1_b   = (const float*)d_in[12];
    const float* head_w  = (const float*)d_in[13];
    const float* head_b  = (const float*)d_in[14];
    float* out = (float*)d_out;

    float *p_stats_b, *p_bn_c1, *p_c1;
    cudaGetSymbolAddress((void**)&p_stats_b, g_stats_b);
    cudaGetSymbolAddress((void**)&p_bn_c1,   g_bn_c1);
    cudaGetSymbolAddress((void**)&p_c1,      g_c1);

    cudaFuncSetAttribute(k_stem, cudaFuncAttributeMaxDynamicSharedMemorySize,
                         STEM_SMEM_B);

    k_bfrag<<<20, 128>>>(stem_w);
    k_stem<<<NSTEMBLK, 128, STEM_SMEM_B>>>(x);
    k_stem_bn_fin<<<64, 256>>>(stem_g, stem_b);
    k_bnpool3<<<(NB*CF*HF*64)/256, 256>>>();
    k_gsample<<<dim3(128,16,2), dim3(128,2)>>>();
    k_roialign<<<(NROI*4*NPIX + 255)/256, 256>>>(box);
    k_conv1<<<dim3(16,8,4), 128>>>(conv1_w);
    k_c1comb<<<(C1TOT + 255)/256, 256>>>(conv1_b);
    k_stats<<<dim3(16,64), 256>>>(p_c1, p_stats_b, C1N);
    k_stats_fin<<<1,64>>>(p_stats_b, bn1_g, bn1_b, p_bn_c1, 1.0f/7056.0f);
    k_bnpool2<<<(NB*64*100 + 255)/256, 256>>>();
    k_conv2<<<16, 256>>>(conv2_w, conv2_b);
    k_fc<<<16, 128>>>(fc1_w, fc1_b, head_w, head_b, out);
}

// round 13
// speedup vs baseline: 1.5604x; 1.1110x over previous
#include <cuda_runtime.h>
#include <math.h>

typedef unsigned long long ull;

// ---------------- problem constants ----------------
#define NB   16
#define HF   128
#define WF   128
#define CF   64
#define CH   704
#define PP   23
#define NPIX (PP*PP)      // 529
#define NROI 176
#define C1N  441          // 21*21
#define C1TOT (NB*64*C1N)

// ---------------- scratch (device globals) ----------------
__device__ float g_stem[(size_t)NB*64*256*256];     // 268 MB fp32 pre-BN
__device__ float g_f  [(size_t)NB*CF*HF*WF];
__device__ float g_xt1[(size_t)NB*CF*HF*WF];
__device__ float g_xt2[(size_t)NB*CF*HF*WF];
__device__ float g_h  [(size_t)NB*CH*NPIX];
__device__ float g_c1p[(size_t)4*C1TOT];
__device__ float g_c1 [(size_t)C1TOT];
__device__ float g_pool[(size_t)NB*64*10*10];
__device__ float g_c2 [(size_t)NB*32*8*8];
__device__ float g_spart_s[64*2048];
__device__ float g_spart_q[64*2048];
__device__ float g_stats_b[64*16*2];
__device__ float g_bn_stem[64*2];
__device__ float g_bn_c1[64*2];

// ---------------- packed f32x2 helpers ----------------
__device__ __forceinline__ ull pack2(float lo, float hi) {
    ull r; asm("mov.b64 %0, {%1, %2};" : "=l"(r) : "f"(lo), "f"(hi)); return r;
}
__device__ __forceinline__ void unpack2(float& lo, float& hi, ull v) {
    asm("mov.b64 {%0, %1}, %2;" : "=f"(lo), "=f"(hi) : "l"(v));
}
__device__ __forceinline__ void ffma2(ull& acc, ull a, ull b) {
    asm("fma.rn.f32x2 %0, %1, %2, %0;" : "+l"(acc) : "l"(a), "l"(b));
}

// ==================================================================
// Kernel 1: stem conv 7x7 s2 p3, NHWC (16,512,512,3) -> fp32 (16,64,256,256)
// block (32,4): tile 32x (x) * 16 rows; thread: 4 rows x 8 oc (oc packed pairs)
// f32x2 FFMA; fused BN partial stats.  [R4/R6/R8-measured configuration]
// ==================================================================
__global__ __launch_bounds__(128) void k_stem(const float* __restrict__ x,
                                              const float* __restrict__ w) {
    __shared__ float s_in[3*37*72];      // 31968 B
    __shared__ ull   s_w2u[588];         // 1176 floats, oc-pair packed
    __shared__ float s_sum[32], s_sq[32];
    float* s_w2 = (float*)s_w2u;

    const int tx = threadIdx.x, ty = threadIdx.y;
    const int tid = ty*32 + tx;
    const int lane = tid & 31, wid = tid >> 5;
    const int bx = blockIdx.x, by = blockIdx.y, b = blockIdx.z;
    const int blockflat = (b*16 + by)*8 + bx;         // 0..2047
    const int ox  = bx*32 + tx;
    const int iy0 = by*32 - 3;
    const int ix0 = bx*64 - 3;

    // input patch load, c fastest in gmem order for coalescing
    for (int i = tid; i < 3*37*69; i += 128) {
        int py = i / 207;
        int rem = i - py*207;
        int px = rem / 3;
        int c  = rem - px*3;
        int ih = iy0 + py, iw = ix0 + px;
        float v = 0.f;
        if (ih >= 0 && ih < 512 && iw >= 0 && iw < 512)
            v = x[((size_t)(b*512 + ih)*512 + iw)*3 + c];
        s_in[c*2664 + py*72 + px] = v;
    }

    for (int ocb = 0; ocb < 8; ocb++) {
        __syncthreads();   // protects s_w2 reuse + prior round's s_sum reads
        for (int i = tid; i < 1176; i += 128)
            s_w2[i] = w[(ocb*8 + (i & 7))*147 + (i >> 3)];
        __syncthreads();

        ull acc2[4][4];
        #pragma unroll
        for (int r = 0; r < 4; r++)
            #pragma unroll
            for (int op = 0; op < 4; op++) acc2[r][op] = 0ull;

        #pragma unroll
        for (int c = 0; c < 3; c++) {
            #pragma unroll
            for (int ky = 0; ky < 7; ky++) {
                const float* ip = &s_in[c*2664 + (2*ty + ky)*72 + 2*tx];
                const ull*   wp = &s_w2u[(c*49 + ky*7)*4];
                #pragma unroll
                for (int kx = 0; kx < 7; kx++) {
                    ull iv[4];
                    #pragma unroll
                    for (int r = 0; r < 4; r++) {
                        float t = ip[r*576 + kx];
                        iv[r] = pack2(t, t);
                    }
                    #pragma unroll
                    for (int op = 0; op < 4; op++) {
                        ull wv = wp[kx*4 + op];
                        #pragma unroll
                        for (int r = 0; r < 4; r++) ffma2(acc2[r][op], iv[r], wv);
                    }
                }
            }
        }

        // store + fused per-oc stats
        #pragma unroll
        for (int op = 0; op < 4; op++) {
            float v0[4], v1[4];
            #pragma unroll
            for (int r = 0; r < 4; r++) unpack2(v0[r], v1[r], acc2[r][op]);
            #pragma unroll
            for (int half = 0; half < 2; half++) {
                int o = 2*op + half;
                int oc = ocb*8 + o;
                float* outp = g_stem + ((size_t)(b*64 + oc)*256 + by*16 + ty)*256 + ox;
                float s = 0.f, q = 0.f;
                #pragma unroll
                for (int r = 0; r < 4; r++) {
                    float v = half ? v1[r] : v0[r];
                    s += v; q += v*v;
                    outp[r*1024] = v;               // 4 rows * 256
                }
                #pragma unroll
                for (int off = 16; off; off >>= 1) {
                    s += __shfl_xor_sync(0xffffffffu, s, off);
                    q += __shfl_xor_sync(0xffffffffu, q, off);
                }
                if (lane == 0) { s_sum[wid*8 + o] = s; s_sq[wid*8 + o] = q; }
            }
        }
        __syncthreads();
        if (tid < 16) {
            int o = tid >> 1;
            if ((tid & 1) == 0) {
                float S = s_sum[o] + s_sum[8+o] + s_sum[16+o] + s_sum[24+o];
                g_spart_s[(ocb*8 + o)*2048 + blockflat] = S;
            } else {
                float Q = s_sq[o] + s_sq[8+o] + s_sq[16+o] + s_sq[24+o];
                g_spart_q[(ocb*8 + o)*2048 + blockflat] = Q;
            }
        }
    }
}

// ==================================================================
// Kernel 2: combine stem stats -> BN scale/bias (deterministic)
// ==================================================================
__global__ void k_stem_bn_fin(const float* __restrict__ g,
                              const float* __restrict__ bta) {
    __shared__ float ss[256], sq[256];
    int oc = blockIdx.x, t = threadIdx.x;
    float S = 0.f, Q = 0.f;
    #pragma unroll
    for (int j = 0; j < 8; j++) {
        int idx = oc*2048 + t*8 + j;
        S += g_spart_s[idx];
        Q += g_spart_q[idx];
    }
    ss[t] = S; sq[t] = Q;
    __syncthreads();
    for (int st = 128; st > 0; st >>= 1) {
        if (t < st) { ss[t] += ss[t+st]; sq[t] += sq[t+st]; }
        __syncthreads();
    }
    if (t == 0) {
        const float invN = 1.0f/(16.0f*65536.0f);
        float m  = ss[0]*invN;
        float v  = sq[0]*invN - m*m;
        float sc = g[oc] * rsqrtf(v + 1e-5f);
        g_bn_stem[oc*2 + 0] = sc;
        g_bn_stem[oc*2 + 1] = bta[oc] - m*sc;
    }
}

// ==================================================================
// Kernel 3: BN + ReLU + maxpool 3x3 s2 p1, vectorized (2 outputs/thread)
// ==================================================================
__global__ void k_bnpool3() {
    int idx = blockIdx.x*256 + threadIdx.x;
    if (idx >= NB*CF*HF*64) return;
    int xo2 = idx & 63;               // output x-pair (2*xo2, 2*xo2+1)
    int yo  = (idx >> 6) & 127;
    int cb  = idx >> 13;              // b*64 + c
    int c   = cb & 63;
    float sc = g_bn_stem[c*2], bi = g_bn_stem[c*2 + 1];
    const float* p = g_stem + (size_t)cb*65536;
    float m0 = -3.402823466e+38f, m1 = m0;
    #pragma unroll
    for (int ky = 0; ky < 3; ky++) {
        int iy = 2*yo - 1 + ky;
        if (iy < 0 || iy > 255) continue;
        const float* row = p + iy*256;
        float4 qv = *reinterpret_cast<const float4*>(row + 4*xo2);
        float a0 = sc*qv.x + bi, a1 = sc*qv.y + bi;
        float a2 = sc*qv.z + bi, a3 = sc*qv.w + bi;
        if (xo2 > 0) {
            float lf = sc*row[4*xo2 - 1] + bi;
            m0 = fmaxf(m0, lf);
        }
        m0 = fmaxf(m0, fmaxf(a0, a1));
        m1 = fmaxf(m1, fmaxf(a1, fmaxf(a2, a3)));
    }
    float2 outv;
    outv.x = fmaxf(m0, 0.f);
    outv.y = fmaxf(m1, 0.f);
    *reinterpret_cast<float2*>(g_f + (size_t)cb*16384 + yo*128 + 2*xo2) = outv;
}

// ==================================================================
// Kernel 4: grid_sample +/-5 deg, geometry hoisted; block (128,4)
// 4-way channel split (16 channels/thread) for deeper MLP
// ==================================================================
__global__ __launch_bounds__(512) void k_gsample() {
    const int xo = threadIdx.x, yo = blockIdx.x;
    const int b = blockIdx.y, which = blockIdx.z;
    const int cq = threadIdx.y;             // 0..3
    const float C5 = 0.99619469809174553f;
    const float S5 = 0.08715574274765817f;
    float gx = (float)(2*xo + 1) * (1.0f/128.0f) - 1.0f;
    float gy = (float)(2*yo + 1) * (1.0f/128.0f) - 1.0f;
    float g0, g1;
    if (which == 0) { g0 =  C5*gx + S5*gy; g1 = -S5*gx + C5*gy; }
    else            { g0 =  C5*gx - S5*gy; g1 =  S5*gx + C5*gy; }
    float ixf = ((g0 + 1.f)*128.f - 1.f)*0.5f;
    float iyf = ((g1 + 1.f)*128.f - 1.f)*0.5f;
    float x0f = floorf(ixf), y0f = floorf(iyf);
    int x0i = (int)x0f, y0i = (int)y0f;
    float lx = ixf - x0f, ly = iyf - y0f;
    float hx = 1.f - lx,  hy = 1.f - ly;
    bool vx0 = (x0i >= 0) && (x0i < 128);
    bool vx1 = (x0i + 1 >= 0) && (x0i + 1 < 128);
    bool vy0 = (y0i >= 0) && (y0i < 128);
    bool vy1 = (y0i + 1 >= 0) && (y0i + 1 < 128);
    int cx0 = min(max(x0i, 0), 127), cx1 = min(max(x0i + 1, 0), 127);
    int cy0 = min(max(y0i, 0), 127), cy1 = min(max(y0i + 1, 0), 127);
    int o00 = cy0*128 + cx0, o01 = cy0*128 + cx1;
    int o10 = cy1*128 + cx0, o11 = cy1*128 + cx1;
    float w00 = (vx0 && vy0) ? hx*hy : 0.f;
    float w01 = (vx1 && vy0) ? lx*hy : 0.f;
    float w10 = (vx0 && vy1) ? hx*ly : 0.f;
    float w11 = (vx1 && vy1) ? lx*ly : 0.f;

    const float* base = g_f + ((size_t)b*64 + cq*16)*16384;
    float* dst = (which ? g_xt2 : g_xt1)
               + ((size_t)b*64 + cq*16)*16384 + yo*128 + xo;
    #pragma unroll 8
    for (int c = 0; c < 16; c++) {
        const float* pl = base + c*16384;
        float v = __ldg(pl + o00)*w00 + __ldg(pl + o01)*w01
                + __ldg(pl + o10)*w10 + __ldg(pl + o11)*w11;
        dst[c*16384] = v;
    }
}

// ==================================================================
// Kernel 5: ROI align (176 rois) -> concat buffer g_h
// thread = (roi, pixel, c-quarter); geometry computed once per 16 channels
// ==================================================================
__global__ __launch_bounds__(256) void k_roialign(const float* __restrict__ box) {
    int idx = blockIdx.x*256 + threadIdx.x;
    if (idx >= NROI*4*NPIX) return;
    int p  = idx % NPIX;
    int t2 = idx / NPIX;
    int cq = t2 & 3;
    int r  = t2 >> 2;

    const float* src; int bb, k, och0;
    if (r < 112) { k = r >> 4; bb = r & 15; src = g_f; och0 = k*64; }
    else {
        int u = r - 112; int grp = u >> 4; bb = u & 15; k = grp & 1;
        src = (grp < 2) ? g_xt1 : g_xt2;
        och0 = 448 + grp*64;
    }
    const float* bp = box + bb*28 + k*4;
    float x1 = bp[0]*0.25f, y1v = bp[1]*0.25f, x2 = bp[2]*0.25f, y2 = bp[3]*0.25f;
    float bw = fmaxf(x2 - x1, 1.0f) * (1.0f/23.0f);
    float bh = fmaxf(y2 - y1v, 1.0f) * (1.0f/23.0f);
    int py = p / 23, px = p - py*23;

    // precompute 4 sample points x 4 taps (offsets + empty-folded weights)
    int   off[4][4];
    float wt [4][4];
    int sp = 0;
    #pragma unroll
    for (int dy = 0; dy < 2; dy++) {
        float posy = (float)py + 0.25f + 0.5f*(float)dy;
        float yv = y1v + posy*bh;
        bool ey = (yv < -1.0f) || (yv > 128.0f);
        float yc  = fminf(fmaxf(yv, 0.f), 127.f);
        float y0f = floorf(yc);
        int y0 = (int)y0f; int y1i = min(y0 + 1, 127);
        float ly = yc - y0f, hy = 1.f - ly;
        #pragma unroll
        for (int dx = 0; dx < 2; dx++) {
            float posx = (float)px + 0.25f + 0.5f*(float)dx;
            float xv = x1 + posx*bw;
            bool ex = (xv < -1.0f) || (xv > 128.0f);
            float xc  = fminf(fmaxf(xv, 0.f), 127.f);
            float x0f = floorf(xc);
            int x0 = (int)x0f; int x1i = min(x0 + 1, 127);
            float lx = xc - x0f, hx = 1.f - lx;
            float m = (ey || ex) ? 0.f : 1.f;
            off[sp][0] = y0*128  + x0;  wt[sp][0] = hy*hx*m;
            off[sp][1] = y0*128  + x1i; wt[sp][1] = hy*lx*m;
            off[sp][2] = y1i*128 + x0;  wt[sp][2] = ly*hx*m;
            off[sp][3] = y1i*128 + x1i; wt[sp][3] = ly*lx*m;
            sp++;
        }
    }

    const float* plane0 = src + ((size_t)bb*64 + cq*16)*16384;
    float* dst = g_h + ((size_t)bb*CH + och0 + cq*16)*NPIX + p;
    #pragma unroll 2
    for (int c = 0; c < 16; c++) {
        const float* pl = plane0 + c*16384;
        float acc = 0.f;
        #pragma unroll
        for (int s2 = 0; s2 < 4; s2++) {
            float v = __ldg(pl + off[s2][0])*wt[s2][0]
                    + __ldg(pl + off[s2][1])*wt[s2][1]
                    + __ldg(pl + off[s2][2])*wt[s2][2]
                    + __ldg(pl + off[s2][3])*wt[s2][3];
            acc += v;
        }
        dst[c*NPIX] = acc * 0.25f;
    }
}

// ==================================================================
// Kernel 6: conv1 704->64 3x3 valid, K-split x4, f32x2 FFMA, oc pairs
// ==================================================================
__global__ __launch_bounds__(128) void k_conv1(const float* __restrict__ w) {
    __shared__ float s_in[16*529];
    __shared__ ull   s_w2u[576];
    float* s_w2 = (float*)s_w2u;
    const int b = blockIdx.x, ocb = blockIdx.y, ks = blockIdx.z;
    const int tid = threadIdx.x;

    int py[4], px[4]; bool val[4];
    #pragma unroll
    for (int j = 0; j < 4; j++) {
        int p = tid + 128*j;
        val[j] = (p < C1N);
        int pc = val[j] ? p : 0;
        py[j] = pc / 21; px[j] = pc - py[j]*21;
    }

    ull acc2[4][4];
    #pragma unroll
    for (int j = 0; j < 4; j++)
        #pragma unroll
        for (int op = 0; op < 4; op++) acc2[j][op] = 0ull;

    for (int icb = ks*11; icb < ks*11 + 11; icb++) {
        __syncthreads();
        for (int i = tid; i < 16*529; i += 128) {
            int ci = i / 529, pp = i - ci*529;
            s_in[i] = g_h[((size_t)b*CH + icb*16 + ci)*NPIX + pp];
        }
        for (int i = tid; i < 1152; i += 128)
            s_w2[i] = w[(size_t)(ocb*8 + (i & 7))*6336 + icb*144 + (i >> 3)];
        __syncthreads();

        for (int ci = 0; ci < 16; ci++) {
            const float* ip = s_in + ci*529;
            const ull*   wp = &s_w2u[ci*9*4];
            #pragma unroll
            for (int ky = 0; ky < 3; ky++) {
                #pragma unroll
                for (int kx = 0; kx < 3; kx++) {
                    ull iv[4];
                    #pragma unroll
                    for (int j = 0; j < 4; j++) {
                        float t = ip[(py[j] + ky)*23 + px[j] + kx];
                        iv[j] = pack2(t, t);
                    }
                    #pragma unroll
                    for (int op = 0; op < 4; op++) {
                        ull wv = wp[(ky*3 + kx)*4 + op];
                        #pragma unroll
                        for (int j = 0; j < 4; j++) ffma2(acc2[j][op], iv[j], wv);
                    }
                }
            }
        }
    }
    #pragma unroll
    for (int op = 0; op < 4; op++) {
        #pragma unroll
        for (int j = 0; j < 4; j++) {
            float lo, hi; unpack2(lo, hi, acc2[j][op]);
            if (val[j]) {
                int oc0 = ocb*8 + 2*op;
                float* dst = g_c1p + (size_t)ks*C1TOT + ((size_t)b*64)*C1N + tid + 128*j;
                dst[(size_t)oc0*C1N]       = lo;
                dst[(size_t)(oc0 + 1)*C1N] = hi;
            }
        }
    }
}

__global__ void k_c1comb(const float* __restrict__ bias) {
    int idx = blockIdx.x*256 + threadIdx.x;
    if (idx >= C1TOT) return;
    int oc = (idx / C1N) & 63;
    float v = g_c1p[idx] + g_c1p[C1TOT + idx] + g_c1p[2*C1TOT + idx]
            + g_c1p[3*C1TOT + idx] + bias[oc];
    g_c1[idx] = v;
}

// ==================================================================
// conv1 BN stats
// ==================================================================
__global__ void k_stats(const float* __restrict__ src, float* __restrict__ partial,
                        int planeN) {
    int b = blockIdx.x, oc = blockIdx.y;
    const float* p = src + ((size_t)b*64 + oc)*(size_t)planeN;
    float s = 0.f, q = 0.f;
    for (int i = threadIdx.x; i < planeN; i += blockDim.x) {
        float v = p[i]; s += v; q += v*v;
    }
    __shared__ float ss[256], sq[256];
    ss[threadIdx.x] = s; sq[threadIdx.x] = q;
    __syncthreads();
    for (int st = 128; st > 0; st >>= 1) {
        if (threadIdx.x < st) {
            ss[threadIdx.x] += ss[threadIdx.x + st];
            sq[threadIdx.x] += sq[threadIdx.x + st];
        }
        __syncthreads();
    }
    if (threadIdx.x == 0) {
        partial[(oc*16 + b)*2 + 0] = ss[0];
        partial[(oc*16 + b)*2 + 1] = sq[0];
    }
}

__global__ void k_stats_fin(const float* __restrict__ partial,
                            const float* __restrict__ g, const float* __restrict__ bta,
                            float* __restrict__ bn, float invN) {
    int oc = threadIdx.x;
    float s = 0.f, q = 0.f;
    for (int b = 0; b < 16; b++) {
        s += partial[(oc*16 + b)*2 + 0];
        q += partial[(oc*16 + b)*2 + 1];
    }
    float m  = s*invN;
    float v  = q*invN - m*m;
    float sc = g[oc] * rsqrtf(v + 1e-5f);
    bn[oc*2 + 0] = sc;
    bn[oc*2 + 1] = bta[oc] - m*sc;
}

// ==================================================================
// Kernel 7: BN + ReLU + maxpool 2x2 s2
// ==================================================================
__global__ void k_bnpool2() {
    int idx = blockIdx.x*256 + threadIdx.x;
    if (idx >= NB*64*100) return;
    int xo = idx % 10;
    int yo = (idx / 10) % 10;
    int cb = idx / 100;
    int c  = cb & 63;
    float sc = g_bn_c1[c*2], bi = g_bn_c1[c*2 + 1];
    const float* p = g_c1 + (size_t)cb*C1N;
    float m = -3.402823466e+38f;
    #pragma unroll
    for (int dy = 0; dy < 2; dy++)
        #pragma unroll
        for (int dx = 0; dx < 2; dx++) {
            float v = sc*p[(2*yo + dy)*21 + 2*xo + dx] + bi;
            m = fmaxf(m, v);
        }
    g_pool[idx] = fmaxf(m, 0.f);
}

// ==================================================================
// Kernel 8: conv2 64->32 3x3 + ReLU, smem-staged; block per image
// ==================================================================
__global__ __launch_bounds__(256) void k_conv2(const float* __restrict__ w,
                                               const float* __restrict__ bias) {
    __shared__ float s_p[64*100];
    int b = blockIdx.x, t = threadIdx.x;
    for (int i = t; i < 6400; i += 256) s_p[i] = g_pool[(size_t)b*6400 + i];
    __syncthreads();
    int oc = t >> 3, py = t & 7;
    float acc[8];
    float bz = bias[oc];
    #pragma unroll
    for (int px = 0; px < 8; px++) acc[px] = bz;
    for (int ic = 0; ic < 64; ic++) {
        const float* ip = s_p + ic*100 + py*10;
        const float* wp = w + (size_t)oc*576 + ic*9;
        float w0 = wp[0], w1 = wp[1], w2 = wp[2];
        float w3 = wp[3], w4 = wp[4], w5 = wp[5];
        float w6 = wp[6], w7 = wp[7], w8 = wp[8];
        #pragma unroll
        for (int px = 0; px < 8; px++) {
            acc[px] += ip[px]*w0      + ip[px+1]*w1    + ip[px+2]*w2
                     + ip[10+px]*w3   + ip[10+px+1]*w4 + ip[10+px+2]*w5
                     + ip[20+px]*w6   + ip[20+px+1]*w7 + ip[20+px+2]*w8;
        }
    }
    float* dst = g_c2 + (size_t)b*2048 + oc*64 + py*8;
    #pragma unroll
    for (int px = 0; px < 8; px++) dst[px] = fmaxf(acc[px], 0.f);
}

// ==================================================================
// Kernel 9: fc1(2048->128)+ReLU then head(128->12)+tanh
// ==================================================================
__global__ void k_fc(const float* __restrict__ fc1w, const float* __restrict__ fc1b,
                     const float* __restrict__ hw,   const float* __restrict__ hb,
                     float* __restrict__ out) {
    __shared__ float sh[128];
    int b = blockIdx.x, j = threadIdx.x;
    const float* xin = g_c2 + (size_t)b*2048;
    const float* wr  = fc1w + (size_t)j*2048;
    float s = fc1b[j];
    for (int k = 0; k < 2048; k++) s += xin[k]*wr[k];
    sh[j] = fmaxf(s, 0.f);
    __syncthreads();
    if (j < 12) {
        float s2 = hb[j];
        const float* hr = hw + j*128;
        for (int k = 0; k < 128; k++) s2 += sh[k]*hr[k];
        out[b*12 + j] = tanhf(s2);
    }
}

// ==================================================================
extern "C" void kernel_launch(void* const* d_in, const int* in_sizes, int n_in,
                              void* d_out, int out_size) {
    const float* x       = (const float*)d_in[0];
    const float* box     = (const float*)d_in[1];
    const float* stem_w  = (const float*)d_in[2];
    const float* stem_g  = (const float*)d_in[3];
    const float* stem_b  = (const float*)d_in[4];
    const float* conv1_w = (const float*)d_in[5];
    const float* conv1_b = (const float*)d_in[6];
    const float* bn1_g   = (const float*)d_in[7];
    const float* bn1_b   = (const float*)d_in[8];
    const float* conv2_w = (const float*)d_in[9];
    const float* conv2_b = (const float*)d_in[10];
    const float* fc1_w   = (const float*)d_in[11];
    const float* fc1_b   = (const float*)d_in[12];
    const float* head_w  = (const float*)d_in[13];
    const float* head_b  = (const float*)d_in[14];
    float* out = (float*)d_out;

    float *p_stats_b, *p_bn_c1, *p_c1;
    cudaGetSymbolAddress((void**)&p_stats_b, g_stats_b);
    cudaGetSymbolAddress((void**)&p_bn_c1,   g_bn_c1);
    cudaGetSymbolAddress((void**)&p_c1,      g_c1);

    k_stem<<<dim3(8,16,16), dim3(32,4)>>>(x, stem_w);
    k_stem_bn_fin<<<64, 256>>>(stem_g, stem_b);
    k_bnpool3<<<(NB*CF*HF*64)/256, 256>>>();
    k_gsample<<<dim3(128,16,2), dim3(128,4)>>>();
    k_roialign<<<(NROI*4*NPIX + 255)/256, 256>>>(box);
    k_conv1<<<dim3(16,8,4), 128>>>(conv1_w);
    k_c1comb<<<(C1TOT + 255)/256, 256>>>(conv1_b);
    k_stats<<<dim3(16,64), 256>>>(p_c1, p_stats_b, C1N);
    k_stats_fin<<<1,64>>>(p_stats_b, bn1_g, bn1_b, p_bn_c1, 1.0f/7056.0f);
    k_bnpool2<<<(NB*64*100 + 255)/256, 256>>>();
    k_conv2<<<16, 256>>>(conv2_w, conv2_b);
    k_fc<<<16, 128>>>(fc1_w, fc1_b, head_w, head_b, out);
}

// round 16
// speedup vs baseline: 1.5682x; 1.0050x over previous
#include <cuda_runtime.h>
#include <math.h>

typedef unsigned long long ull;

// ---------------- problem constants ----------------
#define NB   16
#define HF   128
#define WF   128
#define CF   64
#define CH   704
#define PP   23
#define NPIX (PP*PP)      // 529
#define NROI 176
#define C1N  441          // 21*21
#define C1TOT (NB*64*C1N)

// ---------------- scratch (device globals) ----------------
__device__ float g_stem[(size_t)NB*64*256*256];     // 268 MB fp32 pre-BN
__device__ float g_f  [(size_t)NB*CF*HF*WF];
__device__ float g_xt1[(size_t)NB*CF*HF*WF];
__device__ float g_xt2[(size_t)NB*CF*HF*WF];
__device__ float g_h  [(size_t)NB*CH*NPIX];
__device__ float g_c1p[(size_t)4*C1TOT];
__device__ float g_c1 [(size_t)C1TOT];
__device__ float g_c2 [(size_t)NB*32*8*8];
__device__ float g_spart_s[64*2048];
__device__ float g_spart_q[64*2048];
__device__ float g_stats_b[64*16*2];
__device__ float g_bn_stem[64*2];
__device__ float g_bn_c1[64*2];

// ---------------- packed f32x2 helpers ----------------
__device__ __forceinline__ ull pack2(float lo, float hi) {
    ull r; asm("mov.b64 %0, {%1, %2};" : "=l"(r) : "f"(lo), "f"(hi)); return r;
}
__device__ __forceinline__ void unpack2(float& lo, float& hi, ull v) {
    asm("mov.b64 {%0, %1}, %2;" : "=f"(lo), "=f"(hi) : "l"(v));
}
__device__ __forceinline__ void ffma2(ull& acc, ull a, ull b) {
    asm("fma.rn.f32x2 %0, %1, %2, %0;" : "+l"(acc) : "l"(a), "l"(b));
}

// ==================================================================
// Kernel 1: stem conv 7x7 s2 p3, NHWC (16,512,512,3) -> fp32 (16,64,256,256)
// [R4/R6/R8-measured configuration]
// ==================================================================
__global__ __launch_bounds__(128) void k_stem(const float* __restrict__ x,
                                              const float* __restrict__ w) {
    __shared__ float s_in[3*37*72];
    __shared__ ull   s_w2u[588];
    __shared__ float s_sum[32], s_sq[32];
    float* s_w2 = (float*)s_w2u;

    const int tx = threadIdx.x, ty = threadIdx.y;
    const int tid = ty*32 + tx;
    const int lane = tid & 31, wid = tid >> 5;
    const int bx = blockIdx.x, by = blockIdx.y, b = blockIdx.z;
    const int blockflat = (b*16 + by)*8 + bx;
    const int ox  = bx*32 + tx;
    const int iy0 = by*32 - 3;
    const int ix0 = bx*64 - 3;

    for (int i = tid; i < 3*37*69; i += 128) {
        int py = i / 207;
        int rem = i - py*207;
        int px = rem / 3;
        int c  = rem - px*3;
        int ih = iy0 + py, iw = ix0 + px;
        float v = 0.f;
        if (ih >= 0 && ih < 512 && iw >= 0 && iw < 512)
            v = x[((size_t)(b*512 + ih)*512 + iw)*3 + c];
        s_in[c*2664 + py*72 + px] = v;
    }

    for (int ocb = 0; ocb < 8; ocb++) {
        __syncthreads();
        for (int i = tid; i < 1176; i += 128)
            s_w2[i] = w[(ocb*8 + (i & 7))*147 + (i >> 3)];
        __syncthreads();

        ull acc2[4][4];
        #pragma unroll
        for (int r = 0; r < 4; r++)
            #pragma unroll
            for (int op = 0; op < 4; op++) acc2[r][op] = 0ull;

        #pragma unroll
        for (int c = 0; c < 3; c++) {
            #pragma unroll
            for (int ky = 0; ky < 7; ky++) {
                const float* ip = &s_in[c*2664 + (2*ty + ky)*72 + 2*tx];
                const ull*   wp = &s_w2u[(c*49 + ky*7)*4];
                #pragma unroll
                for (int kx = 0; kx < 7; kx++) {
                    ull iv[4];
                    #pragma unroll
                    for (int r = 0; r < 4; r++) {
                        float t = ip[r*576 + kx];
                        iv[r] = pack2(t, t);
                    }
                    #pragma unroll
                    for (int op = 0; op < 4; op++) {
                        ull wv = wp[kx*4 + op];
                        #pragma unroll
                        for (int r = 0; r < 4; r++) ffma2(acc2[r][op], iv[r], wv);
                    }
                }
            }
        }

        #pragma unroll
        for (int op = 0; op < 4; op++) {
            float v0[4], v1[4];
            #pragma unroll
            for (int r = 0; r < 4; r++) unpack2(v0[r], v1[r], acc2[r][op]);
            #pragma unroll
            for (int half = 0; half < 2; half++) {
                int o = 2*op + half;
                int oc = ocb*8 + o;
                float* outp = g_stem + ((size_t)(b*64 + oc)*256 + by*16 + ty)*256 + ox;
                float s = 0.f, q = 0.f;
                #pragma unroll
                for (int r = 0; r < 4; r++) {
                    float v = half ? v1[r] : v0[r];
                    s += v; q += v*v;
                    outp[r*1024] = v;
                }
                #pragma unroll
                for (int off = 16; off; off >>= 1) {
                    s += __shfl_xor_sync(0xffffffffu, s, off);
                    q += __shfl_xor_sync(0xffffffffu, q, off);
                }
                if (lane == 0) { s_sum[wid*8 + o] = s; s_sq[wid*8 + o] = q; }
            }
        }
        __syncthreads();
        if (tid < 16) {
            int o = tid >> 1;
            if ((tid & 1) == 0) {
                float S = s_sum[o] + s_sum[8+o] + s_sum[16+o] + s_sum[24+o];
                g_spart_s[(ocb*8 + o)*2048 + blockflat] = S;
            } else {
                float Q = s_sq[o] + s_sq[8+o] + s_sq[16+o] + s_sq[24+o];
                g_spart_q[(ocb*8 + o)*2048 + blockflat] = Q;
            }
        }
    }
}

// ==================================================================
// Kernel 2: combine stem stats -> BN scale/bias (deterministic)
// ==================================================================
__global__ void k_stem_bn_fin(const float* __restrict__ g,
                              const float* __restrict__ bta) {
    __shared__ float ss[256], sq[256];
    int oc = blockIdx.x, t = threadIdx.x;
    float S = 0.f, Q = 0.f;
    #pragma unroll
    for (int j = 0; j < 8; j++) {
        int idx = oc*2048 + t*8 + j;
        S += g_spart_s[idx];
        Q += g_spart_q[idx];
    }
    ss[t] = S; sq[t] = Q;
    __syncthreads();
    for (int st = 128; st > 0; st >>= 1) {
        if (t < st) { ss[t] += ss[t+st]; sq[t] += sq[t+st]; }
        __syncthreads();
    }
    if (t == 0) {
        const float invN = 1.0f/(16.0f*65536.0f);
        float m  = ss[0]*invN;
        float v  = sq[0]*invN - m*m;
        float sc = g[oc] * rsqrtf(v + 1e-5f);
        g_bn_stem[oc*2 + 0] = sc;
        g_bn_stem[oc*2 + 1] = bta[oc] - m*sc;
    }
}

// ==================================================================
// Kernel 3: BN + ReLU + maxpool 3x3 s2 p1, vectorized (2 outputs/thread)
// ==================================================================
__global__ void k_bnpool3() {
    int idx = blockIdx.x*256 + threadIdx.x;
    if (idx >= NB*CF*HF*64) return;
    int xo2 = idx & 63;
    int yo  = (idx >> 6) & 127;
    int cb  = idx >> 13;
    int c   = cb & 63;
    float sc = g_bn_stem[c*2], bi = g_bn_stem[c*2 + 1];
    const float* p = g_stem + (size_t)cb*65536;
    float m0 = -3.402823466e+38f, m1 = m0;
    #pragma unroll
    for (int ky = 0; ky < 3; ky++) {
        int iy = 2*yo - 1 + ky;
        if (iy < 0 || iy > 255) continue;
        const float* row = p + iy*256;
        float4 qv = *reinterpret_cast<const float4*>(row + 4*xo2);
        float a0 = sc*qv.x + bi, a1 = sc*qv.y + bi;
        float a2 = sc*qv.z + bi, a3 = sc*qv.w + bi;
        if (xo2 > 0) {
            float lf = sc*row[4*xo2 - 1] + bi;
            m0 = fmaxf(m0, lf);
        }
        m0 = fmaxf(m0, fmaxf(a0, a1));
        m1 = fmaxf(m1, fmaxf(a1, fmaxf(a2, a3)));
    }
    float2 outv;
    outv.x = fmaxf(m0, 0.f);
    outv.y = fmaxf(m1, 0.f);
    *reinterpret_cast<float2*>(g_f + (size_t)cb*16384 + yo*128 + 2*xo2) = outv;
}

// ==================================================================
// Kernel 4: grid_sample +/-5 deg, geometry hoisted; block (128,2)
// [R8-measured best configuration, ~60us]
// ==================================================================
__global__ __launch_bounds__(256) void k_gsample() {
    const int xo = threadIdx.x, yo = blockIdx.x;
    const int b = blockIdx.y, which = blockIdx.z;
    const int chalf = threadIdx.y;
    const float C5 = 0.99619469809174553f;
    const float S5 = 0.08715574274765817f;
    float gx = (float)(2*xo + 1) * (1.0f/128.0f) - 1.0f;
    float gy = (float)(2*yo + 1) * (1.0f/128.0f) - 1.0f;
    float g0, g1;
    if (which == 0) { g0 =  C5*gx + S5*gy; g1 = -S5*gx + C5*gy; }
    else            { g0 =  C5*gx - S5*gy; g1 =  S5*gx + C5*gy; }
    float ixf = ((g0 + 1.f)*128.f - 1.f)*0.5f;
    float iyf = ((g1 + 1.f)*128.f - 1.f)*0.5f;
    float x0f = floorf(ixf), y0f = floorf(iyf);
    int x0i = (int)x0f, y0i = (int)y0f;
    float lx = ixf - x0f, ly = iyf - y0f;
    float hx = 1.f - lx,  hy = 1.f - ly;
    bool vx0 = (x0i >= 0) && (x0i < 128);
    bool vx1 = (x0i + 1 >= 0) && (x0i + 1 < 128);
    bool vy0 = (y0i >= 0) && (y0i < 128);
    bool vy1 = (y0i + 1 >= 0) && (y0i + 1 < 128);
    int cx0 = min(max(x0i, 0), 127), cx1 = min(max(x0i + 1, 0), 127);
    int cy0 = min(max(y0i, 0), 127), cy1 = min(max(y0i + 1, 0), 127);
    int o00 = cy0*128 + cx0, o01 = cy0*128 + cx1;
    int o10 = cy1*128 + cx0, o11 = cy1*128 + cx1;
    float w00 = (vx0 && vy0) ? hx*hy : 0.f;
    float w01 = (vx1 && vy0) ? lx*hy : 0.f;
    float w10 = (vx0 && vy1) ? hx*ly : 0.f;
    float w11 = (vx1 && vy1) ? lx*ly : 0.f;

    const float* base = g_f + ((size_t)b*64 + chalf*32)*16384;
    float* dst = (which ? g_xt2 : g_xt1)
               + ((size_t)b*64 + chalf*32)*16384 + yo*128 + xo;
    #pragma unroll 8
    for (int c = 0; c < 32; c++) {
        const float* pl = base + c*16384;
        float v = __ldg(pl + o00)*w00 + __ldg(pl + o01)*w01
                + __ldg(pl + o10)*w10 + __ldg(pl + o11)*w11;
        dst[c*16384] = v;
    }
}

// ==================================================================
// Kernel 5: ROI align (176 rois) -> concat buffer g_h
// ==================================================================
__global__ __launch_bounds__(256) void k_roialign(const float* __restrict__ box) {
    int idx = blockIdx.x*256 + threadIdx.x;
    if (idx >= NROI*4*NPIX) return;
    int p  = idx % NPIX;
    int t2 = idx / NPIX;
    int cq = t2 & 3;
    int r  = t2 >> 2;

    const float* src; int bb, k, och0;
    if (r < 112) { k = r >> 4; bb = r & 15; src = g_f; och0 = k*64; }
    else {
        int u = r - 112; int grp = u >> 4; bb = u & 15; k = grp & 1;
        src = (grp < 2) ? g_xt1 : g_xt2;
        och0 = 448 + grp*64;
    }
    const float* bp = box + bb*28 + k*4;
    float x1 = bp[0]*0.25f, y1v = bp[1]*0.25f, x2 = bp[2]*0.25f, y2 = bp[3]*0.25f;
    float bw = fmaxf(x2 - x1, 1.0f) * (1.0f/23.0f);
    float bh = fmaxf(y2 - y1v, 1.0f) * (1.0f/23.0f);
    int py = p / 23, px = p - py*23;

    int   off[4][4];
    float wt [4][4];
    int sp = 0;
    #pragma unroll
    for (int dy = 0; dy < 2; dy++) {
        float posy = (float)py + 0.25f + 0.5f*(float)dy;
        float yv = y1v + posy*bh;
        bool ey = (yv < -1.0f) || (yv > 128.0f);
        float yc  = fminf(fmaxf(yv, 0.f), 127.f);
        float y0f = floorf(yc);
        int y0 = (int)y0f; int y1i = min(y0 + 1, 127);
        float ly = yc - y0f, hy = 1.f - ly;
        #pragma unroll
        for (int dx = 0; dx < 2; dx++) {
            float posx = (float)px + 0.25f + 0.5f*(float)dx;
            float xv = x1 + posx*bw;
            bool ex = (xv < -1.0f) || (xv > 128.0f);
            float xc  = fminf(fmaxf(xv, 0.f), 127.f);
            float x0f = floorf(xc);
            int x0 = (int)x0f; int x1i = min(x0 + 1, 127);
            float lx = xc - x0f, hx = 1.f - lx;
            float m = (ey || ex) ? 0.f : 1.f;
            off[sp][0] = y0*128  + x0;  wt[sp][0] = hy*hx*m;
            off[sp][1] = y0*128  + x1i; wt[sp][1] = hy*lx*m;
            off[sp][2] = y1i*128 + x0;  wt[sp][2] = ly*hx*m;
            off[sp][3] = y1i*128 + x1i; wt[sp][3] = ly*lx*m;
            sp++;
        }
    }

    const float* plane0 = src + ((size_t)bb*64 + cq*16)*16384;
    float* dst = g_h + ((size_t)bb*CH + och0 + cq*16)*NPIX + p;
    #pragma unroll 2
    for (int c = 0; c < 16; c++) {
        const float* pl = plane0 + c*16384;
        float acc = 0.f;
        #pragma unroll
        for (int s2 = 0; s2 < 4; s2++) {
            float v = __ldg(pl + off[s2][0])*wt[s2][0]
                    + __ldg(pl + off[s2][1])*wt[s2][1]
                    + __ldg(pl + off[s2][2])*wt[s2][2]
                    + __ldg(pl + off[s2][3])*wt[s2][3];
            acc += v;
        }
        dst[c*NPIX] = acc * 0.25f;
    }
}

// ==================================================================
// Kernel 6: conv1 704->64 3x3 valid, K-split x4, f32x2 FFMA, oc pairs
// ==================================================================
__global__ __launch_bounds__(128) void k_conv1(const float* __restrict__ w) {
    __shared__ float s_in[16*529];
    __shared__ ull   s_w2u[576];
    float* s_w2 = (float*)s_w2u;
    const int b = blockIdx.x, ocb = blockIdx.y, ks = blockIdx.z;
    const int tid = threadIdx.x;

    int py[4], px[4]; bool val[4];
    #pragma unroll
    for (int j = 0; j < 4; j++) {
        int p = tid + 128*j;
        val[j] = (p < C1N);
        int pc = val[j] ? p : 0;
        py[j] = pc / 21; px[j] = pc - py[j]*21;
    }

    ull acc2[4][4];
    #pragma unroll
    for (int j = 0; j < 4; j++)
        #pragma unroll
        for (int op = 0; op < 4; op++) acc2[j][op] = 0ull;

    for (int icb = ks*11; icb < ks*11 + 11; icb++) {
        __syncthreads();
        for (int i = tid; i < 16*529; i += 128) {
            int ci = i / 529, pp = i - ci*529;
            s_in[i] = g_h[((size_t)b*CH + icb*16 + ci)*NPIX + pp];
        }
        for (int i = tid; i < 1152; i += 128)
            s_w2[i] = w[(size_t)(ocb*8 + (i & 7))*6336 + icb*144 + (i >> 3)];
        __syncthreads();

        for (int ci = 0; ci < 16; ci++) {
            const float* ip = s_in + ci*529;
            const ull*   wp = &s_w2u[ci*9*4];
            #pragma unroll
            for (int ky = 0; ky < 3; ky++) {
                #pragma unroll
                for (int kx = 0; kx < 3; kx++) {
                    ull iv[4];
                    #pragma unroll
                    for (int j = 0; j < 4; j++) {
                        float t = ip[(py[j] + ky)*23 + px[j] + kx];
                        iv[j] = pack2(t, t);
                    }
                    #pragma unroll
                    for (int op = 0; op < 4; op++) {
                        ull wv = wp[(ky*3 + kx)*4 + op];
                        #pragma unroll
                        for (int j = 0; j < 4; j++) ffma2(acc2[j][op], iv[j], wv);
                    }
                }
            }
        }
    }
    #pragma unroll
    for (int op = 0; op < 4; op++) {
        #pragma unroll
        for (int j = 0; j < 4; j++) {
            float lo, hi; unpack2(lo, hi, acc2[j][op]);
            if (val[j]) {
                int oc0 = ocb*8 + 2*op;
                float* dst = g_c1p + (size_t)ks*C1TOT + ((size_t)b*64)*C1N + tid + 128*j;
                dst[(size_t)oc0*C1N]       = lo;
                dst[(size_t)(oc0 + 1)*C1N] = hi;
            }
        }
    }
}

// ==================================================================
// Kernel 6b: FUSED combine partials + bias -> g_c1, plus BN stats
// grid (b=16, oc=64), 256 threads. Same accumulation orders as before.
// ==================================================================
__global__ void k_c1fuse(const float* __restrict__ bias) {
    __shared__ float ss[256], sq[256];
    int b = blockIdx.x, oc = blockIdx.y, t = threadIdx.x;
    size_t base = ((size_t)b*64 + oc)*C1N;
    float bz = bias[oc];
    float s = 0.f, q = 0.f;
    for (int i = t; i < C1N; i += 256) {
        size_t idx = base + i;
        float v = g_c1p[idx] + g_c1p[C1TOT + idx] + g_c1p[2*(size_t)C1TOT + idx]
                + g_c1p[3*(size_t)C1TOT + idx] + bz;
        g_c1[idx] = v;
        s += v; q += v*v;
    }
    ss[t] = s; sq[t] = q;
    __syncthreads();
    for (int st = 128; st > 0; st >>= 1) {
        if (t < st) { ss[t] += ss[t+st]; sq[t] += sq[t+st]; }
        __syncthreads();
    }
    if (t == 0) {
        g_stats_b[(oc*16 + b)*2 + 0] = ss[0];
        g_stats_b[(oc*16 + b)*2 + 1] = sq[0];
    }
}

__global__ void k_stats_fin(const float* __restrict__ g, const float* __restrict__ bta) {
    int oc = threadIdx.x;
    float s = 0.f, q = 0.f;
    for (int b = 0; b < 16; b++) {
        s += g_stats_b[(oc*16 + b)*2 + 0];
        q += g_stats_b[(oc*16 + b)*2 + 1];
    }
    const float invN = 1.0f/7056.0f;
    float m  = s*invN;
    float v  = q*invN - m*m;
    float sc = g[oc] * rsqrtf(v + 1e-5f);
    g_bn_c1[oc*2 + 0] = sc;
    g_bn_c1[oc*2 + 1] = bta[oc] - m*sc;
}

// ==================================================================
// Kernel 8: FUSED BN+ReLU+maxpool2 + conv2 64->32 3x3 + ReLU
// block per image; staging applies bnpool2 inline from g_c1
// ==================================================================
__global__ __launch_bounds__(256) void k_conv2(const float* __restrict__ w,
                                               const float* __restrict__ bias) {
    __shared__ float s_p[64*100];
    int b = blockIdx.x, t = threadIdx.x;
    for (int i = t; i < 6400; i += 256) {
        int ic = i / 100;
        int pp = i - ic*100;
        int py = pp / 10, px = pp - py*10;
        float sc = g_bn_c1[ic*2], bi = g_bn_c1[ic*2 + 1];
        const float* pch = g_c1 + ((size_t)b*64 + ic)*C1N;
        float m = -3.402823466e+38f;
        #pragma unroll
        for (int dy = 0; dy < 2; dy++)
            #pragma unroll
            for (int dx = 0; dx < 2; dx++) {
                float v = sc*pch[(2*py + dy)*21 + 2*px + dx] + bi;
                m = fmaxf(m, v);
            }
        s_p[i] = fmaxf(m, 0.f);
    }
    __syncthreads();
    int oc = t >> 3, py = t & 7;
    float acc[8];
    float bz = bias[oc];
    #pragma unroll
    for (int px = 0; px < 8; px++) acc[px] = bz;
    for (int ic = 0; ic < 64; ic++) {
        const float* ip = s_p + ic*100 + py*10;
        const float* wp = w + (size_t)oc*576 + ic*9;
        float w0 = wp[0], w1 = wp[1], w2 = wp[2];
        float w3 = wp[3], w4 = wp[4], w5 = wp[5];
        float w6 = wp[6], w7 = wp[7], w8 = wp[8];
        #pragma unroll
        for (int px = 0; px < 8; px++) {
            acc[px] += ip[px]*w0      + ip[px+1]*w1    + ip[px+2]*w2
                     + ip[10+px]*w3   + ip[10+px+1]*w4 + ip[10+px+2]*w5
                     + ip[20+px]*w6   + ip[20+px+1]*w7 + ip[20+px+2]*w8;
        }
    }
    float* dst = g_c2 + (size_t)b*2048 + oc*64 + py*8;
    #pragma unroll
    for (int px = 0; px < 8; px++) dst[px] = fmaxf(acc[px], 0.f);
}

// ==================================================================
// Kernel 9: fc1(2048->128)+ReLU then head(128->12)+tanh
// ==================================================================
__global__ void k_fc(const float* __restrict__ fc1w, const float* __restrict__ fc1b,
                     const float* __restrict__ hw,   const float* __restrict__ hb,
                     float* __restrict__ out) {
    __shared__ float sh[128];
    int b = blockIdx.x, j = threadIdx.x;
    const float* xin = g_c2 + (size_t)b*2048;
    const float* wr  = fc1w + (size_t)j*2048;
    float s = fc1b[j];
    for (int k = 0; k < 2048; k++) s += xin[k]*wr[k];
    sh[j] = fmaxf(s, 0.f);
    __syncthreads();
    if (j < 12) {
        float s2 = hb[j];
        const float* hr = hw + j*128;
        for (int k = 0; k < 128; k++) s2 += sh[k]*hr[k];
        out[b*12 + j] = tanhf(s2);
    }
}

// ==================================================================
extern "C" void kernel_launch(void* const* d_in, const int* in_sizes, int n_in,
                              void* d_out, int out_size) {
    const float* x       = (const float*)d_in[0];
    const float* box     = (const float*)d_in[1];
    const float* stem_w  = (const float*)d_in[2];
    const float* stem_g  = (const float*)d_in[3];
    const float* stem_b  = (const float*)d_in[4];
    const float* conv1_w = (const float*)d_in[5];
    const float* conv1_b = (const float*)d_in[6];
    const float* bn1_g   = (const float*)d_in[7];
    const float* bn1_b   = (const float*)d_in[8];
    const float* conv2_w = (const float*)d_in[9];
    const float* conv2_b = (const float*)d_in[10];
    const float* fc1_w   = (const float*)d_in[11];
    const float* fc1_b   = (const float*)d_in[12];
    const float* head_w  = (const float*)d_in[13];
    const float* head_b  = (const float*)d_in[14];
    float* out = (float*)d_out;

    k_stem<<<dim3(8,16,16), dim3(32,4)>>>(x, stem_w);
    k_stem_bn_fin<<<64, 256>>>(stem_g, stem_b);
    k_bnpool3<<<(NB*CF*HF*64)/256, 256>>>();
    k_gsample<<<dim3(128,16,2), dim3(128,2)>>>();
    k_roialign<<<(NROI*4*NPIX + 255)/256, 256>>>(box);
    k_conv1<<<dim3(16,8,4), 128>>>(conv1_w);
    k_c1fuse<<<dim3(16,64), 256>>>(conv1_b);
    k_stats_fin<<<1,64>>>(bn1_g, bn1_b);
    k_conv2<<<16, 256>>>(conv2_w, conv2_b);
    k_fc<<<16, 128>>>(fc1_w, fc1_b, head_w, head_b, out);
}